// round 11
// baseline (speedup 1.0000x reference)
#include <cuda_runtime.h>
#include <math.h>
#include <stdint.h>

// Problem constants
#define HIDK   2048
#define NH     16
#define NKV    4
#define HD     128
#define BATCH  2
#define SEQ    2048
#define MROWS  (BATCH * SEQ)     // 4096

// Scratch (device globals; no allocation allowed)
__device__ float g_q[(size_t)MROWS * NH * HD];
__device__ float g_k[(size_t)MROWS * NKV * HD];
__device__ float g_v[(size_t)MROWS * NKV * HD];
__device__ float g_attn[(size_t)MROWS * NH * HD];

// ---------------------------------------------------------------------------
// Common PTX helpers
// ---------------------------------------------------------------------------
__device__ __forceinline__ uint32_t f2tf(float x) {
    uint32_t r;
    asm("cvt.rna.tf32.f32 %0, %1;" : "=r"(r) : "f"(x));
    return r;
}

__device__ __forceinline__ void mma_tf32(float c[4],
                                         uint32_t a0, uint32_t a1, uint32_t a2, uint32_t a3,
                                         uint32_t b0, uint32_t b1) {
    asm volatile(
        "mma.sync.aligned.m16n8k8.row.col.f32.tf32.tf32.f32 "
        "{%0,%1,%2,%3}, {%4,%5,%6,%7}, {%8,%9}, {%0,%1,%2,%3};"
        : "+f"(c[0]), "+f"(c[1]), "+f"(c[2]), "+f"(c[3])
        : "r"(a0), "r"(a1), "r"(a2), "r"(a3), "r"(b0), "r"(b1));
}

__device__ __forceinline__ uint32_t smaddr(const void* p) {
    return (uint32_t)__cvta_generic_to_shared(p);
}

#define CPA16(dst, src) asm volatile("cp.async.cg.shared.global [%0], [%1], 16;\n" :: "r"(dst), "l"(src))
#define CPCOMMIT()      asm volatile("cp.async.commit_group;\n")
#define CPWAIT1()       asm volatile("cp.async.wait_group 1;\n" ::: "memory")
#define CPWAIT0()       asm volatile("cp.async.wait_group 0;\n" ::: "memory")

// ---------------------------------------------------------------------------
// TF32 tensor-core GEMM: C[M,N] = A[M,K] @ B[K,N] + bias[N]
// 128x128 tile, BK=32, 256 threads, double-buffered cp.async, 2 CTAs/SM.
// ---------------------------------------------------------------------------
#define GLA 36
#define GLB 136

__global__ __launch_bounds__(256, 2)
void tf32_gemm_bias(const float* __restrict__ A,
                    const float* __restrict__ B,
                    const float* __restrict__ bias,
                    float* __restrict__ C,
                    int M, int N, int K)
{
    extern __shared__ float sm[];
    float* As = sm;
    float* Bs = sm + 2 * 128 * GLA;

    const int tid  = threadIdx.x;
    const int lane = tid & 31;
    const int warp = tid >> 5;
    const int wr = warp & 3;
    const int wc = warp >> 2;
    const int qr = lane >> 2;
    const int qc = lane & 3;
    const int rowBase = blockIdx.y * 128;
    const int colBase = blockIdx.x * 128;

    float acc[2][8][4];
#pragma unroll
    for (int m = 0; m < 2; ++m)
#pragma unroll
        for (int n = 0; n < 8; ++n)
#pragma unroll
            for (int i = 0; i < 4; ++i) acc[m][n][i] = 0.f;

    const int steps = K >> 5;

    {
        float* as = As;
        float* bs = Bs;
#pragma unroll
        for (int it = 0; it < 4; ++it) {
            int idx = it * 256 + tid;
            int r = idx >> 3, c = (idx & 7) << 2;
            CPA16(smaddr(as + r * GLA + c), A + (size_t)(rowBase + r) * K + c);
            int rb = idx >> 5, cb = (idx & 31) << 2;
            CPA16(smaddr(bs + rb * GLB + cb), B + (size_t)rb * N + colBase + cb);
        }
        CPCOMMIT();
    }

    for (int s = 0; s < steps; ++s) {
        if (s + 1 < steps) {
            int k0 = (s + 1) << 5;
            float* as = As + ((s + 1) & 1) * 128 * GLA;
            float* bs = Bs + ((s + 1) & 1) * 32 * GLB;
#pragma unroll
            for (int it = 0; it < 4; ++it) {
                int idx = it * 256 + tid;
                int r = idx >> 3, c = (idx & 7) << 2;
                CPA16(smaddr(as + r * GLA + c), A + (size_t)(rowBase + r) * K + k0 + c);
                int rb = idx >> 5, cb = (idx & 31) << 2;
                CPA16(smaddr(bs + rb * GLB + cb), B + (size_t)(k0 + rb) * N + colBase + cb);
            }
            CPCOMMIT();
            CPWAIT1();
        } else {
            CPWAIT0();
        }
        __syncthreads();

        const float* as = As + (s & 1) * 128 * GLA + (wr * 32) * GLA;
        const float* bs = Bs + (s & 1) * 32 * GLB + wc * 64;

#pragma unroll
        for (int kk = 0; kk < 4; ++kk) {
            uint32_t af[2][4];
#pragma unroll
            for (int m = 0; m < 2; ++m) {
                const float* ap = as + (m * 16 + qr) * GLA + kk * 8 + qc;
                af[m][0] = f2tf(ap[0]);
                af[m][1] = f2tf(ap[8 * GLA]);
                af[m][2] = f2tf(ap[4]);
                af[m][3] = f2tf(ap[8 * GLA + 4]);
            }
#pragma unroll
            for (int n = 0; n < 8; ++n) {
                const float* bp = bs + (kk * 8 + qc) * GLB + n * 8 + qr;
                uint32_t b0 = f2tf(bp[0]);
                uint32_t b1 = f2tf(bp[4 * GLB]);
                mma_tf32(acc[0][n], af[0][0], af[0][1], af[0][2], af[0][3], b0, b1);
                mma_tf32(acc[1][n], af[1][0], af[1][1], af[1][2], af[1][3], b0, b1);
            }
        }
        __syncthreads();
    }

#pragma unroll
    for (int m = 0; m < 2; ++m) {
        int row = rowBase + wr * 32 + m * 16 + qr;
#pragma unroll
        for (int n = 0; n < 8; ++n) {
            int col = colBase + wc * 64 + n * 8 + qc * 2;
            float bx = bias[col], by = bias[col + 1];
            float2 v0 = make_float2(acc[m][n][0] + bx, acc[m][n][1] + by);
            float2 v1 = make_float2(acc[m][n][2] + bx, acc[m][n][3] + by);
            *(float2*)(C + (size_t)row * N + col)       = v0;
            *(float2*)(C + (size_t)(row + 8) * N + col) = v1;
        }
    }
}

// ---------------------------------------------------------------------------
// Flash attention v11 = v10 with __launch_bounds__(256, 1):
// tells ptxas we run 1 CTA/SM (smem-bound anyway) so it may keep the
// 64-register qa[] Q-cache resident instead of spilling at the 128-reg
// 2-block heuristic cap. No algorithmic change.
// ---------------------------------------------------------------------------
#define FBR 64
#define FBC 64
#define QPITCH 132
#define KPITCH 132
#define VPITCH 136
#define PPITCH 68

__global__ __launch_bounds__(256, 1)
void flash_attn_tf32_kernel(const float* __restrict__ Q,
                            const float* __restrict__ Kg,
                            const float* __restrict__ Vg,
                            float* __restrict__ Og)
{
    extern __shared__ float sm[];
    float* Qs  = sm;                        // [64][QPITCH] fp32 staging
    float* Kp  = Qs + FBR * QPITCH;         // [64][KPITCH] tf32 bits, pair-packed d
    float* Vs  = Kp + FBC * KPITCH;         // [64][VPITCH] fp32 natural
    float* Ps  = Vs + FBC * VPITCH;         // [64][PPITCH] fp32 pair-permuted
    float* ms  = Ps + FBR * PPITCH;
    float* ls  = ms + FBR;
    float* osc = ls + FBR;

    const int tid  = threadIdx.x;
    const int lane = tid & 31;
    const int warp = tid >> 5;
    const int wr = warp & 3;                // 4 warp rows x 16
    const int wc = warp >> 2;               // 2 warp cols
    const int qr = lane >> 2;
    const int qc = lane & 3;

    const int qt  = blockIdx.x;
    const int qh  = blockIdx.y;
    const int b   = blockIdx.z;
    const int kvh = qh >> 2;

    const float scale = 0.08838834764831845f; // 1/sqrt(128)
    const int row0 = wr * 16 + qr;

    // Stage Q tile (64 x 128), pre-scaled, row-major.
    const float* Qbase = Q + ((size_t)(b * SEQ + qt * FBR) * NH + qh) * HD;
#pragma unroll
    for (int it = 0; it < 8; ++it) {
        int idx = it * 256 + tid;
        int r = idx >> 5;
        int c = (idx & 31) << 2;
        float4 v = *(const float4*)(Qbase + (size_t)r * NH * HD + c);
        v.x *= scale; v.y *= scale; v.z *= scale; v.w *= scale;
        *(float4*)(Qs + r * QPITCH + c) = v;
    }
    if (tid < FBR) { ms[tid] = -1e30f; ls[tid] = 0.f; }
    __syncthreads();

    // Convert Q fragments to registers once (reused every kt iteration).
    uint32_t qa[16][4];
    {
        const float* qsw = Qs + (wr * 16 + qr) * QPITCH;
#pragma unroll
        for (int kk = 0; kk < 16; ++kk) {
            const float* ap = qsw + kk * 8 + qc;
            qa[kk][0] = f2tf(ap[0]);
            qa[kk][1] = f2tf(ap[8 * QPITCH]);
            qa[kk][2] = f2tf(ap[4]);
            qa[kk][3] = f2tf(ap[8 * QPITCH + 4]);
        }
    }

    float o[8][4];
#pragma unroll
    for (int n = 0; n < 8; ++n)
#pragma unroll
        for (int i = 0; i < 4; ++i) o[n][i] = 0.f;

    for (int kt = 0; kt <= qt; ++kt) {
        __syncthreads();   // prior-iter reads of Kp/Vs/Ps complete

        const float* Kbase = Kg + ((size_t)(b * SEQ + kt * FBC) * NKV + kvh) * HD;
        const float* Vbase = Vg + ((size_t)(b * SEQ + kt * FBC) * NKV + kvh) * HD;

        // Fill Kp: token-major, d pair-packed (d, d+4) adjacent, tf32 bits.
#pragma unroll
        for (int it = 0; it < 4; ++it) {
            int idx = it * 256 + tid;      // 0..1023
            int r = idx >> 4;              // token 0..63
            int c = (idx & 15) << 3;       // d group of 8
            const float* src = Kbase + (size_t)r * NKV * HD + c;
            float4 x0 = *(const float4*)(src);
            float4 x1 = *(const float4*)(src + 4);
            uint2* dst = (uint2*)(Kp + r * KPITCH + c);
            dst[0] = make_uint2(f2tf(x0.x), f2tf(x1.x));
            dst[1] = make_uint2(f2tf(x0.y), f2tf(x1.y));
            dst[2] = make_uint2(f2tf(x0.z), f2tf(x1.z));
            dst[3] = make_uint2(f2tf(x0.w), f2tf(x1.w));
        }
        // Fill Vs: natural [token][d], float4 conflict-free.
#pragma unroll
        for (int it = 0; it < 8; ++it) {
            int idx = it * 256 + tid;
            int r = idx >> 5;
            int c = (idx & 31) << 2;
            *(float4*)(Vs + r * VPITCH + c) =
                *(const float4*)(Vbase + (size_t)r * NKV * HD + c);
        }
        __syncthreads();

        // --- S = Q @ K^T (warp: 16 rows x 32 cols); B frags = uint2 tf32 bits ---
        float sacc[4][4];
#pragma unroll
        for (int n = 0; n < 4; ++n)
#pragma unroll
            for (int i = 0; i < 4; ++i) sacc[n][i] = 0.f;

#pragma unroll
        for (int kk = 0; kk < 16; ++kk) {
#pragma unroll
            for (int n = 0; n < 4; ++n) {
                uint2 kb = *(const uint2*)(Kp + (wc * 32 + n * 8 + qr) * KPITCH + kk * 8 + qc * 2);
                mma_tf32(sacc[n], qa[kk][0], qa[kk][1], qa[kk][2], qa[kk][3],
                         kb.x, kb.y);
            }
        }

        // Causal mask (original column indices) + store P pair-permuted.
        if (kt == qt) {
#pragma unroll
            for (int n = 0; n < 4; ++n) {
                int col = wc * 32 + n * 8 + qc * 2;
                if (col > row0)         sacc[n][0] = -1e30f;
                if (col + 1 > row0)     sacc[n][1] = -1e30f;
                if (col > row0 + 8)     sacc[n][2] = -1e30f;
                if (col + 1 > row0 + 8) sacc[n][3] = -1e30f;
            }
        }
        {
            int pc = (qc & 1) * 4 + (qc >> 1);   // permuted pos of col j=2*qc
#pragma unroll
            for (int n = 0; n < 4; ++n) {
                int pos = (wc * 4 + n) * 8 + pc;
                Ps[row0 * PPITCH + pos]           = sacc[n][0];
                Ps[row0 * PPITCH + pos + 2]       = sacc[n][1];
                Ps[(row0 + 8) * PPITCH + pos]     = sacc[n][2];
                Ps[(row0 + 8) * PPITCH + pos + 2] = sacc[n][3];
            }
        }
        __syncthreads();

        // --- online softmax: 4 threads per row, float4 vectorized ---
        {
            int row = tid >> 2;
            float* pr = Ps + row * PPITCH + (tid & 3) * 16;
            float4 p0 = *(float4*)(pr);
            float4 p1 = *(float4*)(pr + 4);
            float4 p2 = *(float4*)(pr + 8);
            float4 p3 = *(float4*)(pr + 12);
            float rmax = fmaxf(fmaxf(fmaxf(p0.x, p0.y), fmaxf(p0.z, p0.w)),
                               fmaxf(fmaxf(p1.x, p1.y), fmaxf(p1.z, p1.w)));
            rmax = fmaxf(rmax, fmaxf(fmaxf(fmaxf(p2.x, p2.y), fmaxf(p2.z, p2.w)),
                                     fmaxf(fmaxf(p3.x, p3.y), fmaxf(p3.z, p3.w))));
            rmax = fmaxf(rmax, __shfl_xor_sync(0xffffffffu, rmax, 1));
            rmax = fmaxf(rmax, __shfl_xor_sync(0xffffffffu, rmax, 2));

            float mold = ms[row];
            float mn = fmaxf(mold, rmax);
            p0.x = __expf(p0.x - mn); p0.y = __expf(p0.y - mn);
            p0.z = __expf(p0.z - mn); p0.w = __expf(p0.w - mn);
            p1.x = __expf(p1.x - mn); p1.y = __expf(p1.y - mn);
            p1.z = __expf(p1.z - mn); p1.w = __expf(p1.w - mn);
            p2.x = __expf(p2.x - mn); p2.y = __expf(p2.y - mn);
            p2.z = __expf(p2.z - mn); p2.w = __expf(p2.w - mn);
            p3.x = __expf(p3.x - mn); p3.y = __expf(p3.y - mn);
            p3.z = __expf(p3.z - mn); p3.w = __expf(p3.w - mn);
            *(float4*)(pr)      = p0;
            *(float4*)(pr + 4)  = p1;
            *(float4*)(pr + 8)  = p2;
            *(float4*)(pr + 12) = p3;
            float sum = (p0.x + p0.y + p0.z + p0.w) + (p1.x + p1.y + p1.z + p1.w)
                      + (p2.x + p2.y + p2.z + p2.w) + (p3.x + p3.y + p3.z + p3.w);
            sum += __shfl_xor_sync(0xffffffffu, sum, 1);
            sum += __shfl_xor_sync(0xffffffffu, sum, 2);

            if ((tid & 3) == 0) {
                float corr = __expf(mold - mn);
                ls[row] = ls[row] * corr + sum;
                ms[row] = mn;
                osc[row] = corr;
            }
        }
        __syncthreads();

        // --- rescale accumulator, O += P @ V ---
        {
            float c0 = osc[row0];
            float c1 = osc[row0 + 8];
#pragma unroll
            for (int n = 0; n < 8; ++n) {
                o[n][0] *= c0; o[n][1] *= c0;
                o[n][2] *= c1; o[n][3] *= c1;
            }
        }
#pragma unroll
        for (int kk = 0; kk < 8; ++kk) {
            float2 av0 = *(const float2*)(Ps + row0 * PPITCH + kk * 8 + qc * 2);
            float2 av1 = *(const float2*)(Ps + (row0 + 8) * PPITCH + kk * 8 + qc * 2);
            uint32_t a0 = f2tf(av0.x);
            uint32_t a1 = f2tf(av1.x);
            uint32_t a2 = f2tf(av0.y);
            uint32_t a3 = f2tf(av1.y);
#pragma unroll
            for (int n = 0; n < 8; ++n) {
                const float* bp = Vs + (kk * 8 + qc) * VPITCH + wc * 64 + n * 8 + qr;
                uint32_t b0 = f2tf(bp[0]);
                uint32_t b1 = f2tf(bp[4 * VPITCH]);
                mma_tf32(o[n], a0, a1, a2, a3, b0, b1);
            }
        }
    }

    // Final 1/l normalization + store.
    float inv0 = 1.f / ls[row0];
    float inv1 = 1.f / ls[row0 + 8];
    int srow0 = b * SEQ + qt * FBR + row0;
#pragma unroll
    for (int n = 0; n < 8; ++n) {
        int col = wc * 64 + n * 8 + qc * 2;
        float* p0 = Og + ((size_t)srow0 * NH + qh) * HD + col;
        float* p1 = Og + ((size_t)(srow0 + 8) * NH + qh) * HD + col;
        *(float2*)p0 = make_float2(o[n][0] * inv0, o[n][1] * inv0);
        *(float2*)p1 = make_float2(o[n][2] * inv1, o[n][3] * inv1);
    }
}

// ---------------------------------------------------------------------------
// Launcher
// ---------------------------------------------------------------------------
extern "C" void kernel_launch(void* const* d_in, const int* in_sizes, int n_in,
                              void* d_out, int out_size)
{
    const float* x  = (const float*)d_in[0];
    const float* wq = (const float*)d_in[1];
    const float* bq = (const float*)d_in[2];
    const float* wk = (const float*)d_in[3];
    const float* bk = (const float*)d_in[4];
    const float* wv = (const float*)d_in[5];
    const float* bv = (const float*)d_in[6];
    const float* wo = (const float*)d_in[7];
    const float* bo = (const float*)d_in[8];
    float* out = (float*)d_out;

    float *q, *k, *v, *attn;
    cudaGetSymbolAddress((void**)&q,    g_q);
    cudaGetSymbolAddress((void**)&k,    g_k);
    cudaGetSymbolAddress((void**)&v,    g_v);
    cudaGetSymbolAddress((void**)&attn, g_attn);

    const int gemm_smem = (2 * 128 * GLA + 2 * 32 * GLB) * sizeof(float);
    cudaFuncSetAttribute(tf32_gemm_bias,
                         cudaFuncAttributeMaxDynamicSharedMemorySize, gemm_smem);

    // Projections
    {
        dim3 gq(HIDK / 128, MROWS / 128);
        tf32_gemm_bias<<<gq, 256, gemm_smem>>>(x, wq, bq, q, MROWS, NH * HD, HIDK);
        dim3 gk((NKV * HD) / 128, MROWS / 128);
        tf32_gemm_bias<<<gk, 256, gemm_smem>>>(x, wk, bk, k, MROWS, NKV * HD, HIDK);
        tf32_gemm_bias<<<gk, 256, gemm_smem>>>(x, wv, bv, v, MROWS, NKV * HD, HIDK);
    }

    // Attention
    {
        const int fl_smem = (FBR * QPITCH + FBC * KPITCH + FBC * VPITCH
                             + FBR * PPITCH + 3 * FBR) * sizeof(float);
        cudaFuncSetAttribute(flash_attn_tf32_kernel,
                             cudaFuncAttributeMaxDynamicSharedMemorySize, fl_smem);
        dim3 ga(SEQ / FBR, NH, BATCH);
        flash_attn_tf32_kernel<<<ga, 256, fl_smem>>>(q, k, v, attn);
    }

    // Output projection
    {
        dim3 go(HIDK / 128, MROWS / 128);
        tf32_gemm_bias<<<go, 256, gemm_smem>>>(attn, wo, bo, out, MROWS, HIDK, HIDK);
    }
}

// round 12
// speedup vs baseline: 1.5382x; 1.5382x over previous
#include <cuda_runtime.h>
#include <math.h>
#include <stdint.h>

// Problem constants
#define HIDK   2048
#define NH     16
#define NKV    4
#define HD     128
#define BATCH  2
#define SEQ    2048
#define MROWS  (BATCH * SEQ)     // 4096

// Scratch (device globals; no allocation allowed)
__device__ float g_q[(size_t)MROWS * NH * HD];
__device__ float g_k[(size_t)MROWS * NKV * HD];
__device__ float g_v[(size_t)MROWS * NKV * HD];
__device__ float g_attn[(size_t)MROWS * NH * HD];

// ---------------------------------------------------------------------------
// Common PTX helpers
// ---------------------------------------------------------------------------
__device__ __forceinline__ uint32_t f2tf(float x) {
    uint32_t r;
    asm("cvt.rna.tf32.f32 %0, %1;" : "=r"(r) : "f"(x));
    return r;
}

__device__ __forceinline__ void mma_tf32(float c[4],
                                         uint32_t a0, uint32_t a1, uint32_t a2, uint32_t a3,
                                         uint32_t b0, uint32_t b1) {
    asm volatile(
        "mma.sync.aligned.m16n8k8.row.col.f32.tf32.tf32.f32 "
        "{%0,%1,%2,%3}, {%4,%5,%6,%7}, {%8,%9}, {%0,%1,%2,%3};"
        : "+f"(c[0]), "+f"(c[1]), "+f"(c[2]), "+f"(c[3])
        : "r"(a0), "r"(a1), "r"(a2), "r"(a3), "r"(b0), "r"(b1));
}

__device__ __forceinline__ uint32_t smaddr(const void* p) {
    return (uint32_t)__cvta_generic_to_shared(p);
}

#define CPA16(dst, src) asm volatile("cp.async.cg.shared.global [%0], [%1], 16;\n" :: "r"(dst), "l"(src))
#define CPCOMMIT()      asm volatile("cp.async.commit_group;\n")
#define CPWAIT1()       asm volatile("cp.async.wait_group 1;\n" ::: "memory")
#define CPWAIT0()       asm volatile("cp.async.wait_group 0;\n" ::: "memory")

// ---------------------------------------------------------------------------
// TF32 tensor-core GEMM: C[M,N] = A[M,K] @ B[K,N] + bias[N]
// 128x128 tile, BK=32, 256 threads, double-buffered cp.async, 2 CTAs/SM.
// (R10's measured-best gemm configuration.)
// ---------------------------------------------------------------------------
#define GLA 36
#define GLB 136

__global__ __launch_bounds__(256, 2)
void tf32_gemm_bias(const float* __restrict__ A,
                    const float* __restrict__ B,
                    const float* __restrict__ bias,
                    float* __restrict__ C,
                    int M, int N, int K)
{
    extern __shared__ float sm[];
    float* As = sm;
    float* Bs = sm + 2 * 128 * GLA;

    const int tid  = threadIdx.x;
    const int lane = tid & 31;
    const int warp = tid >> 5;
    const int wr = warp & 3;
    const int wc = warp >> 2;
    const int qr = lane >> 2;
    const int qc = lane & 3;
    const int rowBase = blockIdx.y * 128;
    const int colBase = blockIdx.x * 128;

    float acc[2][8][4];
#pragma unroll
    for (int m = 0; m < 2; ++m)
#pragma unroll
        for (int n = 0; n < 8; ++n)
#pragma unroll
            for (int i = 0; i < 4; ++i) acc[m][n][i] = 0.f;

    const int steps = K >> 5;

    {
        float* as = As;
        float* bs = Bs;
#pragma unroll
        for (int it = 0; it < 4; ++it) {
            int idx = it * 256 + tid;
            int r = idx >> 3, c = (idx & 7) << 2;
            CPA16(smaddr(as + r * GLA + c), A + (size_t)(rowBase + r) * K + c);
            int rb = idx >> 5, cb = (idx & 31) << 2;
            CPA16(smaddr(bs + rb * GLB + cb), B + (size_t)rb * N + colBase + cb);
        }
        CPCOMMIT();
    }

    for (int s = 0; s < steps; ++s) {
        if (s + 1 < steps) {
            int k0 = (s + 1) << 5;
            float* as = As + ((s + 1) & 1) * 128 * GLA;
            float* bs = Bs + ((s + 1) & 1) * 32 * GLB;
#pragma unroll
            for (int it = 0; it < 4; ++it) {
                int idx = it * 256 + tid;
                int r = idx >> 3, c = (idx & 7) << 2;
                CPA16(smaddr(as + r * GLA + c), A + (size_t)(rowBase + r) * K + k0 + c);
                int rb = idx >> 5, cb = (idx & 31) << 2;
                CPA16(smaddr(bs + rb * GLB + cb), B + (size_t)(k0 + rb) * N + colBase + cb);
            }
            CPCOMMIT();
            CPWAIT1();
        } else {
            CPWAIT0();
        }
        __syncthreads();

        const float* as = As + (s & 1) * 128 * GLA + (wr * 32) * GLA;
        const float* bs = Bs + (s & 1) * 32 * GLB + wc * 64;

#pragma unroll
        for (int kk = 0; kk < 4; ++kk) {
            uint32_t af[2][4];
#pragma unroll
            for (int m = 0; m < 2; ++m) {
                const float* ap = as + (m * 16 + qr) * GLA + kk * 8 + qc;
                af[m][0] = f2tf(ap[0]);
                af[m][1] = f2tf(ap[8 * GLA]);
                af[m][2] = f2tf(ap[4]);
                af[m][3] = f2tf(ap[8 * GLA + 4]);
            }
#pragma unroll
            for (int n = 0; n < 8; ++n) {
                const float* bp = bs + (kk * 8 + qc) * GLB + n * 8 + qr;
                uint32_t b0 = f2tf(bp[0]);
                uint32_t b1 = f2tf(bp[4 * GLB]);
                mma_tf32(acc[0][n], af[0][0], af[0][1], af[0][2], af[0][3], b0, b1);
                mma_tf32(acc[1][n], af[1][0], af[1][1], af[1][2], af[1][3], b0, b1);
            }
        }
        __syncthreads();
    }

#pragma unroll
    for (int m = 0; m < 2; ++m) {
        int row = rowBase + wr * 32 + m * 16 + qr;
#pragma unroll
        for (int n = 0; n < 8; ++n) {
            int col = colBase + wc * 64 + n * 8 + qc * 2;
            float bx = bias[col], by = bias[col + 1];
            float2 v0 = make_float2(acc[m][n][0] + bx, acc[m][n][1] + by);
            float2 v1 = make_float2(acc[m][n][2] + bx, acc[m][n][3] + by);
            *(float2*)(C + (size_t)row * N + col)       = v0;
            *(float2*)(C + (size_t)(row + 8) * N + col) = v1;
        }
    }
}

// ---------------------------------------------------------------------------
// Flash attention: R4's 522us kernel VERBATIM.
//   Q staged row-major fp32 (pitch 132) -> per-warp tf32 register cache;
//   K pair-packed fp32 (pitch 132), cvt in QK loop (float2 B frags);
//   V natural fp32 (pitch 136), cvt in PV loop;
//   P pair-permuted fp32 (pitch 68), float4 softmax.
// ---------------------------------------------------------------------------
#define FBR 64
#define FBC 64
#define QPITCH 132
#define KPITCH 132
#define VPITCH 136
#define PPITCH 68

__global__ __launch_bounds__(256)
void flash_attn_tf32_kernel(const float* __restrict__ Q,
                            const float* __restrict__ Kg,
                            const float* __restrict__ Vg,
                            float* __restrict__ Og)
{
    extern __shared__ float sm[];
    float* Qs  = sm;                        // [64][QPITCH] (staging only)
    float* Kp  = Qs + FBR * QPITCH;         // [64][KPITCH] pair-packed d (fp32)
    float* Vs  = Kp + FBC * KPITCH;         // [64][VPITCH] natural
    float* Ps  = Vs + FBC * VPITCH;         // [64][PPITCH] pair-permuted cols
    float* ms  = Ps + FBR * PPITCH;
    float* ls  = ms + FBR;
    float* osc = ls + FBR;

    const int tid  = threadIdx.x;
    const int lane = tid & 31;
    const int warp = tid >> 5;
    const int wr = warp & 3;                // 4 warp rows x 16
    const int wc = warp >> 2;               // 2 warp cols
    const int qr = lane >> 2;
    const int qc = lane & 3;

    const int qt  = blockIdx.x;
    const int qh  = blockIdx.y;
    const int b   = blockIdx.z;
    const int kvh = qh >> 2;

    const float scale = 0.08838834764831845f; // 1/sqrt(128)

    // Stage Q tile (64 x 128), pre-scaled, row-major.
    const float* Qbase = Q + ((size_t)(b * SEQ + qt * FBR) * NH + qh) * HD;
#pragma unroll
    for (int it = 0; it < 8; ++it) {
        int idx = it * 256 + tid;
        int r = idx >> 5;
        int c = (idx & 31) << 2;
        float4 v = *(const float4*)(Qbase + (size_t)r * NH * HD + c);
        v.x *= scale; v.y *= scale; v.z *= scale; v.w *= scale;
        *(float4*)(Qs + r * QPITCH + c) = v;
    }
    if (tid < FBR) { ms[tid] = -1e30f; ls[tid] = 0.f; }
    __syncthreads();

    // Convert Q fragments to registers once (reused every kt iteration).
    uint32_t qa[16][4];
    {
        const float* qsw = Qs + (wr * 16 + qr) * QPITCH;
#pragma unroll
        for (int kk = 0; kk < 16; ++kk) {
            const float* ap = qsw + kk * 8 + qc;
            qa[kk][0] = f2tf(ap[0]);
            qa[kk][1] = f2tf(ap[8 * QPITCH]);
            qa[kk][2] = f2tf(ap[4]);
            qa[kk][3] = f2tf(ap[8 * QPITCH + 4]);
        }
    }

    float o[8][4];
#pragma unroll
    for (int n = 0; n < 8; ++n)
#pragma unroll
        for (int i = 0; i < 4; ++i) o[n][i] = 0.f;

    const int row0 = wr * 16 + qr;

    for (int kt = 0; kt <= qt; ++kt) {
        __syncthreads();   // prior-iter reads of Kp/Vs/Ps complete

        const float* Kbase = Kg + ((size_t)(b * SEQ + kt * FBC) * NKV + kvh) * HD;
        const float* Vbase = Vg + ((size_t)(b * SEQ + kt * FBC) * NKV + kvh) * HD;

        // Fill Kp: token-major, d pair-packed: pairs (d, d+4) adjacent (fp32).
#pragma unroll
        for (int it = 0; it < 4; ++it) {
            int idx = it * 256 + tid;      // 0..1023
            int r = idx >> 4;              // token 0..63
            int c = (idx & 15) << 3;       // d group of 8
            const float* src = Kbase + (size_t)r * NKV * HD + c;
            float4 x0 = *(const float4*)(src);
            float4 x1 = *(const float4*)(src + 4);
            float* dst = Kp + r * KPITCH + c;
            *(float2*)(dst + 0) = make_float2(x0.x, x1.x);
            *(float2*)(dst + 2) = make_float2(x0.y, x1.y);
            *(float2*)(dst + 4) = make_float2(x0.z, x1.z);
            *(float2*)(dst + 6) = make_float2(x0.w, x1.w);
        }
        // Fill Vs: natural [token][d], float4 conflict-free.
#pragma unroll
        for (int it = 0; it < 8; ++it) {
            int idx = it * 256 + tid;
            int r = idx >> 5;
            int c = (idx & 31) << 2;
            *(float4*)(Vs + r * VPITCH + c) =
                *(const float4*)(Vbase + (size_t)r * NKV * HD + c);
        }
        __syncthreads();

        // --- S = Q @ K^T (warp: 16 rows x 32 cols); B frags = float2 from Kp ---
        float sacc[4][4];
#pragma unroll
        for (int n = 0; n < 4; ++n)
#pragma unroll
            for (int i = 0; i < 4; ++i) sacc[n][i] = 0.f;

#pragma unroll
        for (int kk = 0; kk < 16; ++kk) {
#pragma unroll
            for (int n = 0; n < 4; ++n) {
                const float* bp = Kp + (wc * 32 + n * 8 + qr) * KPITCH + kk * 8 + qc * 2;
                float2 bv = *(const float2*)bp;
                mma_tf32(sacc[n], qa[kk][0], qa[kk][1], qa[kk][2], qa[kk][3],
                         f2tf(bv.x), f2tf(bv.y));
            }
        }

        // Causal mask (original column indices) + store P pair-permuted.
        if (kt == qt) {
#pragma unroll
            for (int n = 0; n < 4; ++n) {
                int col = wc * 32 + n * 8 + qc * 2;
                if (col > row0)         sacc[n][0] = -1e30f;
                if (col + 1 > row0)     sacc[n][1] = -1e30f;
                if (col > row0 + 8)     sacc[n][2] = -1e30f;
                if (col + 1 > row0 + 8) sacc[n][3] = -1e30f;
            }
        }
        {
            int pc = (qc & 1) * 4 + (qc >> 1);   // permuted pos of col j=2*qc
#pragma unroll
            for (int n = 0; n < 4; ++n) {
                int pos = (wc * 4 + n) * 8 + pc;
                Ps[row0 * PPITCH + pos]           = sacc[n][0];
                Ps[row0 * PPITCH + pos + 2]       = sacc[n][1];
                Ps[(row0 + 8) * PPITCH + pos]     = sacc[n][2];
                Ps[(row0 + 8) * PPITCH + pos + 2] = sacc[n][3];
            }
        }
        __syncthreads();

        // --- online softmax: 4 threads per row, float4 vectorized ---
        {
            int row = tid >> 2;
            float* pr = Ps + row * PPITCH + (tid & 3) * 16;
            float4 p0 = *(float4*)(pr);
            float4 p1 = *(float4*)(pr + 4);
            float4 p2 = *(float4*)(pr + 8);
            float4 p3 = *(float4*)(pr + 12);
            float rmax = fmaxf(fmaxf(fmaxf(p0.x, p0.y), fmaxf(p0.z, p0.w)),
                               fmaxf(fmaxf(p1.x, p1.y), fmaxf(p1.z, p1.w)));
            rmax = fmaxf(rmax, fmaxf(fmaxf(fmaxf(p2.x, p2.y), fmaxf(p2.z, p2.w)),
                                     fmaxf(fmaxf(p3.x, p3.y), fmaxf(p3.z, p3.w))));
            rmax = fmaxf(rmax, __shfl_xor_sync(0xffffffffu, rmax, 1));
            rmax = fmaxf(rmax, __shfl_xor_sync(0xffffffffu, rmax, 2));

            float mold = ms[row];
            float mn = fmaxf(mold, rmax);
            p0.x = __expf(p0.x - mn); p0.y = __expf(p0.y - mn);
            p0.z = __expf(p0.z - mn); p0.w = __expf(p0.w - mn);
            p1.x = __expf(p1.x - mn); p1.y = __expf(p1.y - mn);
            p1.z = __expf(p1.z - mn); p1.w = __expf(p1.w - mn);
            p2.x = __expf(p2.x - mn); p2.y = __expf(p2.y - mn);
            p2.z = __expf(p2.z - mn); p2.w = __expf(p2.w - mn);
            p3.x = __expf(p3.x - mn); p3.y = __expf(p3.y - mn);
            p3.z = __expf(p3.z - mn); p3.w = __expf(p3.w - mn);
            *(float4*)(pr)      = p0;
            *(float4*)(pr + 4)  = p1;
            *(float4*)(pr + 8)  = p2;
            *(float4*)(pr + 12) = p3;
            float sum = (p0.x + p0.y + p0.z + p0.w) + (p1.x + p1.y + p1.z + p1.w)
                      + (p2.x + p2.y + p2.z + p2.w) + (p3.x + p3.y + p3.z + p3.w);
            sum += __shfl_xor_sync(0xffffffffu, sum, 1);
            sum += __shfl_xor_sync(0xffffffffu, sum, 2);

            if ((tid & 3) == 0) {
                float corr = __expf(mold - mn);
                ls[row] = ls[row] * corr + sum;
                ms[row] = mn;
                osc[row] = corr;
            }
        }
        __syncthreads();

        // --- rescale accumulator, O += P @ V ---
        {
            float c0 = osc[row0];
            float c1 = osc[row0 + 8];
#pragma unroll
            for (int n = 0; n < 8; ++n) {
                o[n][0] *= c0; o[n][1] *= c0;
                o[n][2] *= c1; o[n][3] *= c1;
            }
        }
#pragma unroll
        for (int kk = 0; kk < 8; ++kk) {
            const float* ap = Ps + row0 * PPITCH + kk * 8 + qc * 2;
            float2 av0 = *(const float2*)ap;
            float2 av1 = *(const float2*)(ap + 8 * PPITCH);
            uint32_t a0 = f2tf(av0.x);   // (row qr,   k)
            uint32_t a1 = f2tf(av1.x);   // (row qr+8, k)
            uint32_t a2 = f2tf(av0.y);   // (row qr,   k+4)
            uint32_t a3 = f2tf(av1.y);   // (row qr+8, k+4)
#pragma unroll
            for (int n = 0; n < 8; ++n) {
                const float* bp = Vs + (kk * 8 + qc) * VPITCH + wc * 64 + n * 8 + qr;
                uint32_t b0 = f2tf(bp[0]);
                uint32_t b1 = f2tf(bp[4 * VPITCH]);
                mma_tf32(o[n], a0, a1, a2, a3, b0, b1);
            }
        }
    }

    // Final 1/l normalization + store.
    float inv0 = 1.f / ls[row0];
    float inv1 = 1.f / ls[row0 + 8];
    int srow0 = b * SEQ + qt * FBR + row0;
#pragma unroll
    for (int n = 0; n < 8; ++n) {
        int col = wc * 64 + n * 8 + qc * 2;
        float* p0 = Og + ((size_t)srow0 * NH + qh) * HD + col;
        float* p1 = Og + ((size_t)(srow0 + 8) * NH + qh) * HD + col;
        *(float2*)p0 = make_float2(o[n][0] * inv0, o[n][1] * inv0);
        *(float2*)p1 = make_float2(o[n][2] * inv1, o[n][3] * inv1);
    }
}

// ---------------------------------------------------------------------------
// Launcher
// ---------------------------------------------------------------------------
extern "C" void kernel_launch(void* const* d_in, const int* in_sizes, int n_in,
                              void* d_out, int out_size)
{
    const float* x  = (const float*)d_in[0];
    const float* wq = (const float*)d_in[1];
    const float* bq = (const float*)d_in[2];
    const float* wk = (const float*)d_in[3];
    const float* bk = (const float*)d_in[4];
    const float* wv = (const float*)d_in[5];
    const float* bv = (const float*)d_in[6];
    const float* wo = (const float*)d_in[7];
    const float* bo = (const float*)d_in[8];
    float* out = (float*)d_out;

    float *q, *k, *v, *attn;
    cudaGetSymbolAddress((void**)&q,    g_q);
    cudaGetSymbolAddress((void**)&k,    g_k);
    cudaGetSymbolAddress((void**)&v,    g_v);
    cudaGetSymbolAddress((void**)&attn, g_attn);

    const int gemm_smem = (2 * 128 * GLA + 2 * 32 * GLB) * sizeof(float);
    cudaFuncSetAttribute(tf32_gemm_bias,
                         cudaFuncAttributeMaxDynamicSharedMemorySize, gemm_smem);

    // Projections
    {
        dim3 gq(HIDK / 128, MROWS / 128);
        tf32_gemm_bias<<<gq, 256, gemm_smem>>>(x, wq, bq, q, MROWS, NH * HD, HIDK);
        dim3 gk((NKV * HD) / 128, MROWS / 128);
        tf32_gemm_bias<<<gk, 256, gemm_smem>>>(x, wk, bk, k, MROWS, NKV * HD, HIDK);
        tf32_gemm_bias<<<gk, 256, gemm_smem>>>(x, wv, bv, v, MROWS, NKV * HD, HIDK);
    }

    // Attention
    {
        const int fl_smem = (FBR * QPITCH + FBC * KPITCH + FBC * VPITCH
                             + FBR * PPITCH + 3 * FBR) * sizeof(float);
        cudaFuncSetAttribute(flash_attn_tf32_kernel,
                             cudaFuncAttributeMaxDynamicSharedMemorySize, fl_smem);
        dim3 ga(SEQ / FBR, NH, BATCH);
        flash_attn_tf32_kernel<<<ga, 256, fl_smem>>>(q, k, v, attn);
    }

    // Output projection
    {
        dim3 go(HIDK / 128, MROWS / 128);
        tf32_gemm_bias<<<go, 256, gemm_smem>>>(attn, wo, bo, out, MROWS, HIDK, HIDK);
    }
}

// round 13
// speedup vs baseline: 1.5681x; 1.0195x over previous
#include <cuda_runtime.h>
#include <math.h>
#include <stdint.h>

// Problem constants
#define HIDK   2048
#define NH     16
#define NKV    4
#define HD     128
#define BATCH  2
#define SEQ    2048
#define MROWS  (BATCH * SEQ)     // 4096

// Scratch (device globals; no allocation allowed)
__device__ float g_q[(size_t)MROWS * NH * HD];
__device__ float g_k[(size_t)MROWS * NKV * HD];
__device__ float g_v[(size_t)MROWS * NKV * HD];
__device__ float g_attn[(size_t)MROWS * NH * HD];
// tf32-preconverted operands
__device__ float g_xt[(size_t)MROWS * HIDK];
__device__ float g_wqt[(size_t)HIDK * NH * HD];
__device__ float g_wkt[(size_t)HIDK * NKV * HD];
__device__ float g_wvt[(size_t)HIDK * NKV * HD];
__device__ float g_wot[(size_t)HIDK * HIDK];
__device__ float g_attnt[(size_t)MROWS * NH * HD];

// ---------------------------------------------------------------------------
// Common PTX helpers
// ---------------------------------------------------------------------------
__device__ __forceinline__ uint32_t f2tf(float x) {
    uint32_t r;
    asm("cvt.rna.tf32.f32 %0, %1;" : "=r"(r) : "f"(x));
    return r;
}

__device__ __forceinline__ void mma_tf32(float c[4],
                                         uint32_t a0, uint32_t a1, uint32_t a2, uint32_t a3,
                                         uint32_t b0, uint32_t b1) {
    asm volatile(
        "mma.sync.aligned.m16n8k8.row.col.f32.tf32.tf32.f32 "
        "{%0,%1,%2,%3}, {%4,%5,%6,%7}, {%8,%9}, {%0,%1,%2,%3};"
        : "+f"(c[0]), "+f"(c[1]), "+f"(c[2]), "+f"(c[3])
        : "r"(a0), "r"(a1), "r"(a2), "r"(a3), "r"(b0), "r"(b1));
}

__device__ __forceinline__ uint32_t smaddr(const void* p) {
    return (uint32_t)__cvta_generic_to_shared(p);
}

#define CPA16(dst, src) asm volatile("cp.async.cg.shared.global [%0], [%1], 16;\n" :: "r"(dst), "l"(src))
#define CPCOMMIT()      asm volatile("cp.async.commit_group;\n")
#define CPWAIT1()       asm volatile("cp.async.wait_group 1;\n" ::: "memory")
#define CPWAIT0()       asm volatile("cp.async.wait_group 0;\n" ::: "memory")

// ---------------------------------------------------------------------------
// Elementwise tf32 pre-conversion: out[i] = bits(cvt.rna.tf32(in[i]))
// ---------------------------------------------------------------------------
__global__ __launch_bounds__(256)
void cvt_tf32_kernel(const float* __restrict__ in, float* __restrict__ out, int n4)
{
    int i = blockIdx.x * 256 + threadIdx.x;
    if (i < n4) {
        float4 v = ((const float4*)in)[i];
        uint4 o;
        o.x = f2tf(v.x);
        o.y = f2tf(v.y);
        o.z = f2tf(v.z);
        o.w = f2tf(v.w);
        ((uint4*)out)[i] = o;
    }
}

// ---------------------------------------------------------------------------
// TF32 tensor-core GEMM on PRE-CONVERTED operands (no cvt in the loop):
// C[M,N] = A[M,K] @ B[K,N] + bias[N]. A,B hold tf32-bit floats.
// 128x128 tile, BK=32, 256 threads, double-buffered cp.async, 2 CTAs/SM.
// ---------------------------------------------------------------------------
#define GLA 36
#define GLB 136

__global__ __launch_bounds__(256, 2)
void tf32_gemm_bias_pre(const float* __restrict__ A,
                        const float* __restrict__ B,
                        const float* __restrict__ bias,
                        float* __restrict__ C,
                        int M, int N, int K)
{
    extern __shared__ float sm[];
    float* As = sm;
    float* Bs = sm + 2 * 128 * GLA;

    const int tid  = threadIdx.x;
    const int lane = tid & 31;
    const int warp = tid >> 5;
    const int wr = warp & 3;
    const int wc = warp >> 2;
    const int qr = lane >> 2;
    const int qc = lane & 3;
    const int rowBase = blockIdx.y * 128;
    const int colBase = blockIdx.x * 128;

    float acc[2][8][4];
#pragma unroll
    for (int m = 0; m < 2; ++m)
#pragma unroll
        for (int n = 0; n < 8; ++n)
#pragma unroll
            for (int i = 0; i < 4; ++i) acc[m][n][i] = 0.f;

    const int steps = K >> 5;

    {
        float* as = As;
        float* bs = Bs;
#pragma unroll
        for (int it = 0; it < 4; ++it) {
            int idx = it * 256 + tid;
            int r = idx >> 3, c = (idx & 7) << 2;
            CPA16(smaddr(as + r * GLA + c), A + (size_t)(rowBase + r) * K + c);
            int rb = idx >> 5, cb = (idx & 31) << 2;
            CPA16(smaddr(bs + rb * GLB + cb), B + (size_t)rb * N + colBase + cb);
        }
        CPCOMMIT();
    }

    for (int s = 0; s < steps; ++s) {
        if (s + 1 < steps) {
            int k0 = (s + 1) << 5;
            float* as = As + ((s + 1) & 1) * 128 * GLA;
            float* bs = Bs + ((s + 1) & 1) * 32 * GLB;
#pragma unroll
            for (int it = 0; it < 4; ++it) {
                int idx = it * 256 + tid;
                int r = idx >> 3, c = (idx & 7) << 2;
                CPA16(smaddr(as + r * GLA + c), A + (size_t)(rowBase + r) * K + k0 + c);
                int rb = idx >> 5, cb = (idx & 31) << 2;
                CPA16(smaddr(bs + rb * GLB + cb), B + (size_t)(k0 + rb) * N + colBase + cb);
            }
            CPCOMMIT();
            CPWAIT1();
        } else {
            CPWAIT0();
        }
        __syncthreads();

        const float* as = As + (s & 1) * 128 * GLA + (wr * 32) * GLA;
        const float* bs = Bs + (s & 1) * 32 * GLB + wc * 64;

#pragma unroll
        for (int kk = 0; kk < 4; ++kk) {
            uint32_t af[2][4];
#pragma unroll
            for (int m = 0; m < 2; ++m) {
                const float* ap = as + (m * 16 + qr) * GLA + kk * 8 + qc;
                af[m][0] = __float_as_uint(ap[0]);
                af[m][1] = __float_as_uint(ap[8 * GLA]);
                af[m][2] = __float_as_uint(ap[4]);
                af[m][3] = __float_as_uint(ap[8 * GLA + 4]);
            }
#pragma unroll
            for (int n = 0; n < 8; ++n) {
                const float* bp = bs + (kk * 8 + qc) * GLB + n * 8 + qr;
                uint32_t b0 = __float_as_uint(bp[0]);
                uint32_t b1 = __float_as_uint(bp[4 * GLB]);
                mma_tf32(acc[0][n], af[0][0], af[0][1], af[0][2], af[0][3], b0, b1);
                mma_tf32(acc[1][n], af[1][0], af[1][1], af[1][2], af[1][3], b0, b1);
            }
        }
        __syncthreads();
    }

#pragma unroll
    for (int m = 0; m < 2; ++m) {
        int row = rowBase + wr * 32 + m * 16 + qr;
#pragma unroll
        for (int n = 0; n < 8; ++n) {
            int col = colBase + wc * 64 + n * 8 + qc * 2;
            float bx = bias[col], by = bias[col + 1];
            float2 v0 = make_float2(acc[m][n][0] + bx, acc[m][n][1] + by);
            float2 v1 = make_float2(acc[m][n][2] + bx, acc[m][n][3] + by);
            *(float2*)(C + (size_t)row * N + col)       = v0;
            *(float2*)(C + (size_t)(row + 8) * N + col) = v1;
        }
    }
}

// ---------------------------------------------------------------------------
// Flash attention: R12's 522us kernel VERBATIM (frozen).
// ---------------------------------------------------------------------------
#define FBR 64
#define FBC 64
#define QPITCH 132
#define KPITCH 132
#define VPITCH 136
#define PPITCH 68

__global__ __launch_bounds__(256)
void flash_attn_tf32_kernel(const float* __restrict__ Q,
                            const float* __restrict__ Kg,
                            const float* __restrict__ Vg,
                            float* __restrict__ Og)
{
    extern __shared__ float sm[];
    float* Qs  = sm;                        // [64][QPITCH] (staging only)
    float* Kp  = Qs + FBR * QPITCH;         // [64][KPITCH] pair-packed d (fp32)
    float* Vs  = Kp + FBC * KPITCH;         // [64][VPITCH] natural
    float* Ps  = Vs + FBC * VPITCH;         // [64][PPITCH] pair-permuted cols
    float* ms  = Ps + FBR * PPITCH;
    float* ls  = ms + FBR;
    float* osc = ls + FBR;

    const int tid  = threadIdx.x;
    const int lane = tid & 31;
    const int warp = tid >> 5;
    const int wr = warp & 3;                // 4 warp rows x 16
    const int wc = warp >> 2;               // 2 warp cols
    const int qr = lane >> 2;
    const int qc = lane & 3;

    const int qt  = blockIdx.x;
    const int qh  = blockIdx.y;
    const int b   = blockIdx.z;
    const int kvh = qh >> 2;

    const float scale = 0.08838834764831845f; // 1/sqrt(128)

    // Stage Q tile (64 x 128), pre-scaled, row-major.
    const float* Qbase = Q + ((size_t)(b * SEQ + qt * FBR) * NH + qh) * HD;
#pragma unroll
    for (int it = 0; it < 8; ++it) {
        int idx = it * 256 + tid;
        int r = idx >> 5;
        int c = (idx & 31) << 2;
        float4 v = *(const float4*)(Qbase + (size_t)r * NH * HD + c);
        v.x *= scale; v.y *= scale; v.z *= scale; v.w *= scale;
        *(float4*)(Qs + r * QPITCH + c) = v;
    }
    if (tid < FBR) { ms[tid] = -1e30f; ls[tid] = 0.f; }
    __syncthreads();

    // Convert Q fragments to registers once (reused every kt iteration).
    uint32_t qa[16][4];
    {
        const float* qsw = Qs + (wr * 16 + qr) * QPITCH;
#pragma unroll
        for (int kk = 0; kk < 16; ++kk) {
            const float* ap = qsw + kk * 8 + qc;
            qa[kk][0] = f2tf(ap[0]);
            qa[kk][1] = f2tf(ap[8 * QPITCH]);
            qa[kk][2] = f2tf(ap[4]);
            qa[kk][3] = f2tf(ap[8 * QPITCH + 4]);
        }
    }

    float o[8][4];
#pragma unroll
    for (int n = 0; n < 8; ++n)
#pragma unroll
        for (int i = 0; i < 4; ++i) o[n][i] = 0.f;

    const int row0 = wr * 16 + qr;

    for (int kt = 0; kt <= qt; ++kt) {
        __syncthreads();   // prior-iter reads of Kp/Vs/Ps complete

        const float* Kbase = Kg + ((size_t)(b * SEQ + kt * FBC) * NKV + kvh) * HD;
        const float* Vbase = Vg + ((size_t)(b * SEQ + kt * FBC) * NKV + kvh) * HD;

        // Fill Kp: token-major, d pair-packed: pairs (d, d+4) adjacent (fp32).
#pragma unroll
        for (int it = 0; it < 4; ++it) {
            int idx = it * 256 + tid;      // 0..1023
            int r = idx >> 4;              // token 0..63
            int c = (idx & 15) << 3;       // d group of 8
            const float* src = Kbase + (size_t)r * NKV * HD + c;
            float4 x0 = *(const float4*)(src);
            float4 x1 = *(const float4*)(src + 4);
            float* dst = Kp + r * KPITCH + c;
            *(float2*)(dst + 0) = make_float2(x0.x, x1.x);
            *(float2*)(dst + 2) = make_float2(x0.y, x1.y);
            *(float2*)(dst + 4) = make_float2(x0.z, x1.z);
            *(float2*)(dst + 6) = make_float2(x0.w, x1.w);
        }
        // Fill Vs: natural [token][d], float4 conflict-free.
#pragma unroll
        for (int it = 0; it < 8; ++it) {
            int idx = it * 256 + tid;
            int r = idx >> 5;
            int c = (idx & 31) << 2;
            *(float4*)(Vs + r * VPITCH + c) =
                *(const float4*)(Vbase + (size_t)r * NKV * HD + c);
        }
        __syncthreads();

        // --- S = Q @ K^T (warp: 16 rows x 32 cols); B frags = float2 from Kp ---
        float sacc[4][4];
#pragma unroll
        for (int n = 0; n < 4; ++n)
#pragma unroll
            for (int i = 0; i < 4; ++i) sacc[n][i] = 0.f;

#pragma unroll
        for (int kk = 0; kk < 16; ++kk) {
#pragma unroll
            for (int n = 0; n < 4; ++n) {
                const float* bp = Kp + (wc * 32 + n * 8 + qr) * KPITCH + kk * 8 + qc * 2;
                float2 bv = *(const float2*)bp;
                mma_tf32(sacc[n], qa[kk][0], qa[kk][1], qa[kk][2], qa[kk][3],
                         f2tf(bv.x), f2tf(bv.y));
            }
        }

        // Causal mask (original column indices) + store P pair-permuted.
        if (kt == qt) {
#pragma unroll
            for (int n = 0; n < 4; ++n) {
                int col = wc * 32 + n * 8 + qc * 2;
                if (col > row0)         sacc[n][0] = -1e30f;
                if (col + 1 > row0)     sacc[n][1] = -1e30f;
                if (col > row0 + 8)     sacc[n][2] = -1e30f;
                if (col + 1 > row0 + 8) sacc[n][3] = -1e30f;
            }
        }
        {
            int pc = (qc & 1) * 4 + (qc >> 1);   // permuted pos of col j=2*qc
#pragma unroll
            for (int n = 0; n < 4; ++n) {
                int pos = (wc * 4 + n) * 8 + pc;
                Ps[row0 * PPITCH + pos]           = sacc[n][0];
                Ps[row0 * PPITCH + pos + 2]       = sacc[n][1];
                Ps[(row0 + 8) * PPITCH + pos]     = sacc[n][2];
                Ps[(row0 + 8) * PPITCH + pos + 2] = sacc[n][3];
            }
        }
        __syncthreads();

        // --- online softmax: 4 threads per row, float4 vectorized ---
        {
            int row = tid >> 2;
            float* pr = Ps + row * PPITCH + (tid & 3) * 16;
            float4 p0 = *(float4*)(pr);
            float4 p1 = *(float4*)(pr + 4);
            float4 p2 = *(float4*)(pr + 8);
            float4 p3 = *(float4*)(pr + 12);
            float rmax = fmaxf(fmaxf(fmaxf(p0.x, p0.y), fmaxf(p0.z, p0.w)),
                               fmaxf(fmaxf(p1.x, p1.y), fmaxf(p1.z, p1.w)));
            rmax = fmaxf(rmax, fmaxf(fmaxf(fmaxf(p2.x, p2.y), fmaxf(p2.z, p2.w)),
                                     fmaxf(fmaxf(p3.x, p3.y), fmaxf(p3.z, p3.w))));
            rmax = fmaxf(rmax, __shfl_xor_sync(0xffffffffu, rmax, 1));
            rmax = fmaxf(rmax, __shfl_xor_sync(0xffffffffu, rmax, 2));

            float mold = ms[row];
            float mn = fmaxf(mold, rmax);
            p0.x = __expf(p0.x - mn); p0.y = __expf(p0.y - mn);
            p0.z = __expf(p0.z - mn); p0.w = __expf(p0.w - mn);
            p1.x = __expf(p1.x - mn); p1.y = __expf(p1.y - mn);
            p1.z = __expf(p1.z - mn); p1.w = __expf(p1.w - mn);
            p2.x = __expf(p2.x - mn); p2.y = __expf(p2.y - mn);
            p2.z = __expf(p2.z - mn); p2.w = __expf(p2.w - mn);
            p3.x = __expf(p3.x - mn); p3.y = __expf(p3.y - mn);
            p3.z = __expf(p3.z - mn); p3.w = __expf(p3.w - mn);
            *(float4*)(pr)      = p0;
            *(float4*)(pr + 4)  = p1;
            *(float4*)(pr + 8)  = p2;
            *(float4*)(pr + 12) = p3;
            float sum = (p0.x + p0.y + p0.z + p0.w) + (p1.x + p1.y + p1.z + p1.w)
                      + (p2.x + p2.y + p2.z + p2.w) + (p3.x + p3.y + p3.z + p3.w);
            sum += __shfl_xor_sync(0xffffffffu, sum, 1);
            sum += __shfl_xor_sync(0xffffffffu, sum, 2);

            if ((tid & 3) == 0) {
                float corr = __expf(mold - mn);
                ls[row] = ls[row] * corr + sum;
                ms[row] = mn;
                osc[row] = corr;
            }
        }
        __syncthreads();

        // --- rescale accumulator, O += P @ V ---
        {
            float c0 = osc[row0];
            float c1 = osc[row0 + 8];
#pragma unroll
            for (int n = 0; n < 8; ++n) {
                o[n][0] *= c0; o[n][1] *= c0;
                o[n][2] *= c1; o[n][3] *= c1;
            }
        }
#pragma unroll
        for (int kk = 0; kk < 8; ++kk) {
            const float* ap = Ps + row0 * PPITCH + kk * 8 + qc * 2;
            float2 av0 = *(const float2*)ap;
            float2 av1 = *(const float2*)(ap + 8 * PPITCH);
            uint32_t a0 = f2tf(av0.x);   // (row qr,   k)
            uint32_t a1 = f2tf(av1.x);   // (row qr+8, k)
            uint32_t a2 = f2tf(av0.y);   // (row qr,   k+4)
            uint32_t a3 = f2tf(av1.y);   // (row qr+8, k+4)
#pragma unroll
            for (int n = 0; n < 8; ++n) {
                const float* bp = Vs + (kk * 8 + qc) * VPITCH + wc * 64 + n * 8 + qr;
                uint32_t b0 = f2tf(bp[0]);
                uint32_t b1 = f2tf(bp[4 * VPITCH]);
                mma_tf32(o[n], a0, a1, a2, a3, b0, b1);
            }
        }
    }

    // Final 1/l normalization + store.
    float inv0 = 1.f / ls[row0];
    float inv1 = 1.f / ls[row0 + 8];
    int srow0 = b * SEQ + qt * FBR + row0;
#pragma unroll
    for (int n = 0; n < 8; ++n) {
        int col = wc * 64 + n * 8 + qc * 2;
        float* p0 = Og + ((size_t)srow0 * NH + qh) * HD + col;
        float* p1 = Og + ((size_t)(srow0 + 8) * NH + qh) * HD + col;
        *(float2*)p0 = make_float2(o[n][0] * inv0, o[n][1] * inv0);
        *(float2*)p1 = make_float2(o[n][2] * inv1, o[n][3] * inv1);
    }
}

// ---------------------------------------------------------------------------
// Launcher
// ---------------------------------------------------------------------------
extern "C" void kernel_launch(void* const* d_in, const int* in_sizes, int n_in,
                              void* d_out, int out_size)
{
    const float* x  = (const float*)d_in[0];
    const float* wq = (const float*)d_in[1];
    const float* bq = (const float*)d_in[2];
    const float* wk = (const float*)d_in[3];
    const float* bk = (const float*)d_in[4];
    const float* wv = (const float*)d_in[5];
    const float* bv = (const float*)d_in[6];
    const float* wo = (const float*)d_in[7];
    const float* bo = (const float*)d_in[8];
    float* out = (float*)d_out;

    float *q, *k, *v, *attn;
    float *xt, *wqt, *wkt, *wvt, *wot, *attnt;
    cudaGetSymbolAddress((void**)&q,     g_q);
    cudaGetSymbolAddress((void**)&k,     g_k);
    cudaGetSymbolAddress((void**)&v,     g_v);
    cudaGetSymbolAddress((void**)&attn,  g_attn);
    cudaGetSymbolAddress((void**)&xt,    g_xt);
    cudaGetSymbolAddress((void**)&wqt,   g_wqt);
    cudaGetSymbolAddress((void**)&wkt,   g_wkt);
    cudaGetSymbolAddress((void**)&wvt,   g_wvt);
    cudaGetSymbolAddress((void**)&wot,   g_wot);
    cudaGetSymbolAddress((void**)&attnt, g_attnt);

    // tf32 pre-conversion passes
    {
        int n4x = (MROWS * HIDK) / 4;            // 2097152
        cvt_tf32_kernel<<<(n4x + 255) / 256, 256>>>(x, xt, n4x);
        int n4q = (HIDK * NH * HD) / 4;          // 1048576
        cvt_tf32_kernel<<<(n4q + 255) / 256, 256>>>(wq, wqt, n4q);
        int n4k = (HIDK * NKV * HD) / 4;         // 262144
        cvt_tf32_kernel<<<(n4k + 255) / 256, 256>>>(wk, wkt, n4k);
        cvt_tf32_kernel<<<(n4k + 255) / 256, 256>>>(wv, wvt, n4k);
        int n4o = (HIDK * HIDK) / 4;             // 1048576
        cvt_tf32_kernel<<<(n4o + 255) / 256, 256>>>(wo, wot, n4o);
    }

    const int gemm_smem = (2 * 128 * GLA + 2 * 32 * GLB) * sizeof(float);
    cudaFuncSetAttribute(tf32_gemm_bias_pre,
                         cudaFuncAttributeMaxDynamicSharedMemorySize, gemm_smem);

    // Projections (pre-converted operands, no cvt in loop)
    {
        dim3 gq(HIDK / 128, MROWS / 128);
        tf32_gemm_bias_pre<<<gq, 256, gemm_smem>>>(xt, wqt, bq, q, MROWS, NH * HD, HIDK);
        dim3 gk((NKV * HD) / 128, MROWS / 128);
        tf32_gemm_bias_pre<<<gk, 256, gemm_smem>>>(xt, wkt, bk, k, MROWS, NKV * HD, HIDK);
        tf32_gemm_bias_pre<<<gk, 256, gemm_smem>>>(xt, wvt, bv, v, MROWS, NKV * HD, HIDK);
    }

    // Attention (frozen R12 kernel)
    {
        const int fl_smem = (FBR * QPITCH + FBC * KPITCH + FBC * VPITCH
                             + FBR * PPITCH + 3 * FBR) * sizeof(float);
        cudaFuncSetAttribute(flash_attn_tf32_kernel,
                             cudaFuncAttributeMaxDynamicSharedMemorySize, fl_smem);
        dim3 ga(SEQ / FBR, NH, BATCH);
        flash_attn_tf32_kernel<<<ga, 256, fl_smem>>>(q, k, v, attn);
    }

    // attn -> tf32 bits, then output projection
    {
        int n4a = (MROWS * HIDK) / 4;
        cvt_tf32_kernel<<<(n4a + 255) / 256, 256>>>(attn, attnt, n4a);
        dim3 go(HIDK / 128, MROWS / 128);
        tf32_gemm_bias_pre<<<go, 256, gemm_smem>>>(attnt, wot, bo, out, MROWS, HIDK, HIDK);
    }
}

// round 14
// speedup vs baseline: 1.9440x; 1.2397x over previous
#include <cuda_runtime.h>
#include <cuda_fp16.h>
#include <math.h>
#include <stdint.h>

// Problem constants
#define HIDK   2048
#define NH     16
#define NKV    4
#define HD     128
#define BATCH  2
#define SEQ    2048
#define MROWS  (BATCH * SEQ)     // 4096

// Scratch (device globals; no allocation allowed)
__device__ float  g_q[(size_t)MROWS * NH * HD];
__device__ float  g_k[(size_t)MROWS * NKV * HD];
__device__ float  g_v[(size_t)MROWS * NKV * HD];
__device__ float  g_attn[(size_t)MROWS * NH * HD];
// fp16 operands for the GEMMs
__device__ __half g_xh[(size_t)MROWS * HIDK];
__device__ __half g_attnh[(size_t)MROWS * HIDK];
__device__ __half g_wqh[(size_t)(NH * HD) * HIDK];    // transposed [N][K]
__device__ __half g_wkh[(size_t)(NKV * HD) * HIDK];   // transposed
__device__ __half g_wvh[(size_t)(NKV * HD) * HIDK];   // transposed
__device__ __half g_woh[(size_t)HIDK * HIDK];         // transposed

// ---------------------------------------------------------------------------
// Common PTX helpers
// ---------------------------------------------------------------------------
__device__ __forceinline__ uint32_t f2tf(float x) {
    uint32_t r;
    asm("cvt.rna.tf32.f32 %0, %1;" : "=r"(r) : "f"(x));
    return r;
}

__device__ __forceinline__ void mma_tf32(float c[4],
                                         uint32_t a0, uint32_t a1, uint32_t a2, uint32_t a3,
                                         uint32_t b0, uint32_t b1) {
    asm volatile(
        "mma.sync.aligned.m16n8k8.row.col.f32.tf32.tf32.f32 "
        "{%0,%1,%2,%3}, {%4,%5,%6,%7}, {%8,%9}, {%0,%1,%2,%3};"
        : "+f"(c[0]), "+f"(c[1]), "+f"(c[2]), "+f"(c[3])
        : "r"(a0), "r"(a1), "r"(a2), "r"(a3), "r"(b0), "r"(b1));
}

__device__ __forceinline__ void mma_f16(float c[4],
                                        uint32_t a0, uint32_t a1, uint32_t a2, uint32_t a3,
                                        uint32_t b0, uint32_t b1) {
    asm volatile(
        "mma.sync.aligned.m16n8k16.row.col.f32.f16.f16.f32 "
        "{%0,%1,%2,%3}, {%4,%5,%6,%7}, {%8,%9}, {%0,%1,%2,%3};"
        : "+f"(c[0]), "+f"(c[1]), "+f"(c[2]), "+f"(c[3])
        : "r"(a0), "r"(a1), "r"(a2), "r"(a3), "r"(b0), "r"(b1));
}

__device__ __forceinline__ uint32_t smaddr(const void* p) {
    return (uint32_t)__cvta_generic_to_shared(p);
}

#define CPA16(dst, src) asm volatile("cp.async.cg.shared.global [%0], [%1], 16;\n" :: "r"(dst), "l"(src))
#define CPCOMMIT()      asm volatile("cp.async.commit_group;\n")
#define CPWAIT1()       asm volatile("cp.async.wait_group 1;\n" ::: "memory")
#define CPWAIT0()       asm volatile("cp.async.wait_group 0;\n" ::: "memory")

// ---------------------------------------------------------------------------
// fp32 -> fp16 elementwise convert (for A operands: x, attn)
// ---------------------------------------------------------------------------
__global__ __launch_bounds__(256)
void cvt_h_kernel(const float* __restrict__ in, __half* __restrict__ out, int n4)
{
    int i = blockIdx.x * 256 + threadIdx.x;
    if (i < n4) {
        float4 v = ((const float4*)in)[i];
        __half2 h0 = __floats2half2_rn(v.x, v.y);
        __half2 h1 = __floats2half2_rn(v.z, v.w);
        uint2 o;
        o.x = *reinterpret_cast<uint32_t*>(&h0);
        o.y = *reinterpret_cast<uint32_t*>(&h1);
        ((uint2*)out)[i] = o;
    }
}

// ---------------------------------------------------------------------------
// fp32 [K][N] -> fp16 transposed [N][K] (for weights)
// 32x32 tiles, 256 threads.
// ---------------------------------------------------------------------------
__global__ __launch_bounds__(256)
void cvt_h_transpose_kernel(const float* __restrict__ in, __half* __restrict__ out,
                            int K, int N)
{
    __shared__ float t[32][33];
    int nb = blockIdx.x * 32;
    int kb = blockIdx.y * 32;
    int tx = threadIdx.x & 31;
    int ty = threadIdx.x >> 5;     // 0..7
#pragma unroll
    for (int i = 0; i < 4; ++i)
        t[ty + i * 8][tx] = in[(size_t)(kb + ty + i * 8) * N + nb + tx];
    __syncthreads();
#pragma unroll
    for (int i = 0; i < 4; ++i)
        out[(size_t)(nb + ty + i * 8) * K + kb + tx] = __float2half_rn(t[tx][ty + i * 8]);
}

// ---------------------------------------------------------------------------
// FP16 tensor-core GEMM: C[M,N] = A[M,K] @ Bt[N,K]^T + bias[N]  (fp32 accum)
// A: fp16 [M][K] row-major; Bt: fp16 [N][K] (pre-transposed weights).
// 128x128 tile, BK=32, 256 threads (8 warps 4x2), warp tile 32x64,
// double-buffered cp.async. All fragment loads are natural b32 LDS.
// ---------------------------------------------------------------------------
#define HPA 40   // A smem pitch (halves); conflict-free (qr*80+qc*4 banks distinct)
#define HPB 40   // B smem pitch (halves)

__global__ __launch_bounds__(256, 2)
void h_gemm_bias(const __half* __restrict__ A,
                 const __half* __restrict__ Bt,
                 const float* __restrict__ bias,
                 float* __restrict__ C,
                 int M, int N, int K)
{
    extern __shared__ __half hsm[];
    __half* As = hsm;                        // [2][128*HPA]
    __half* Bs = hsm + 2 * 128 * HPA;        // [2][128*HPB]

    const int tid  = threadIdx.x;
    const int lane = tid & 31;
    const int warp = tid >> 5;
    const int wr = warp & 3;
    const int wc = warp >> 2;
    const int qr = lane >> 2;
    const int qc = lane & 3;
    const int rowBase = blockIdx.y * 128;
    const int colBase = blockIdx.x * 128;

    float acc[2][8][4];
#pragma unroll
    for (int m = 0; m < 2; ++m)
#pragma unroll
        for (int n = 0; n < 8; ++n)
#pragma unroll
            for (int i = 0; i < 4; ++i) acc[m][n][i] = 0.f;

    const int steps = K >> 5;

    // stage 0 fill
    {
        __half* as = As;
        __half* bs = Bs;
#pragma unroll
        for (int it = 0; it < 2; ++it) {
            int idx = it * 256 + tid;          // 0..511
            int r = idx >> 2;                  // 0..127
            int c = (idx & 3) << 3;            // half offset 0,8,16,24
            CPA16(smaddr(as + r * HPA + c), A + (size_t)(rowBase + r) * K + c);
            CPA16(smaddr(bs + r * HPB + c), Bt + (size_t)(colBase + r) * K + c);
        }
        CPCOMMIT();
    }

    for (int s = 0; s < steps; ++s) {
        if (s + 1 < steps) {
            int k0 = (s + 1) << 5;
            __half* as = As + ((s + 1) & 1) * 128 * HPA;
            __half* bs = Bs + ((s + 1) & 1) * 128 * HPB;
#pragma unroll
            for (int it = 0; it < 2; ++it) {
                int idx = it * 256 + tid;
                int r = idx >> 2;
                int c = (idx & 3) << 3;
                CPA16(smaddr(as + r * HPA + c), A + (size_t)(rowBase + r) * K + k0 + c);
                CPA16(smaddr(bs + r * HPB + c), Bt + (size_t)(colBase + r) * K + k0 + c);
            }
            CPCOMMIT();
            CPWAIT1();
        } else {
            CPWAIT0();
        }
        __syncthreads();

        const __half* as = As + (s & 1) * 128 * HPA + (wr * 32) * HPA;
        const __half* bs = Bs + (s & 1) * 128 * HPB + (wc * 64) * HPB;

#pragma unroll
        for (int kk = 0; kk < 2; ++kk) {       // k16 per mma, BK=32
            uint32_t af[2][4];
#pragma unroll
            for (int m = 0; m < 2; ++m) {
                const __half* ap = as + (m * 16 + qr) * HPA + kk * 16 + qc * 2;
                af[m][0] = *(const uint32_t*)(ap);
                af[m][1] = *(const uint32_t*)(ap + 8 * HPA);
                af[m][2] = *(const uint32_t*)(ap + 8);
                af[m][3] = *(const uint32_t*)(ap + 8 * HPA + 8);
            }
#pragma unroll
            for (int n = 0; n < 8; ++n) {
                const __half* bp = bs + (n * 8 + qr) * HPB + kk * 16 + qc * 2;
                uint32_t b0 = *(const uint32_t*)(bp);
                uint32_t b1 = *(const uint32_t*)(bp + 8);
                mma_f16(acc[0][n], af[0][0], af[0][1], af[0][2], af[0][3], b0, b1);
                mma_f16(acc[1][n], af[1][0], af[1][1], af[1][2], af[1][3], b0, b1);
            }
        }
        __syncthreads();
    }

    // Epilogue: add bias, fp32 stores.
#pragma unroll
    for (int m = 0; m < 2; ++m) {
        int row = rowBase + wr * 32 + m * 16 + qr;
#pragma unroll
        for (int n = 0; n < 8; ++n) {
            int col = colBase + wc * 64 + n * 8 + qc * 2;
            float bx = bias[col], by = bias[col + 1];
            float2 v0 = make_float2(acc[m][n][0] + bx, acc[m][n][1] + by);
            float2 v1 = make_float2(acc[m][n][2] + bx, acc[m][n][3] + by);
            *(float2*)(C + (size_t)row * N + col)       = v0;
            *(float2*)(C + (size_t)(row + 8) * N + col) = v1;
        }
    }
}

// ---------------------------------------------------------------------------
// Flash attention: R12's 522us kernel VERBATIM (frozen).
// ---------------------------------------------------------------------------
#define FBR 64
#define FBC 64
#define QPITCH 132
#define KPITCH 132
#define VPITCH 136
#define PPITCH 68

__global__ __launch_bounds__(256)
void flash_attn_tf32_kernel(const float* __restrict__ Q,
                            const float* __restrict__ Kg,
                            const float* __restrict__ Vg,
                            float* __restrict__ Og)
{
    extern __shared__ float sm[];
    float* Qs  = sm;                        // [64][QPITCH] (staging only)
    float* Kp  = Qs + FBR * QPITCH;         // [64][KPITCH] pair-packed d (fp32)
    float* Vs  = Kp + FBC * KPITCH;         // [64][VPITCH] natural
    float* Ps  = Vs + FBC * VPITCH;         // [64][PPITCH] pair-permuted cols
    float* ms  = Ps + FBR * PPITCH;
    float* ls  = ms + FBR;
    float* osc = ls + FBR;

    const int tid  = threadIdx.x;
    const int lane = tid & 31;
    const int warp = tid >> 5;
    const int wr = warp & 3;                // 4 warp rows x 16
    const int wc = warp >> 2;               // 2 warp cols
    const int qr = lane >> 2;
    const int qc = lane & 3;

    const int qt  = blockIdx.x;
    const int qh  = blockIdx.y;
    const int b   = blockIdx.z;
    const int kvh = qh >> 2;

    const float scale = 0.08838834764831845f; // 1/sqrt(128)

    // Stage Q tile (64 x 128), pre-scaled, row-major.
    const float* Qbase = Q + ((size_t)(b * SEQ + qt * FBR) * NH + qh) * HD;
#pragma unroll
    for (int it = 0; it < 8; ++it) {
        int idx = it * 256 + tid;
        int r = idx >> 5;
        int c = (idx & 31) << 2;
        float4 v = *(const float4*)(Qbase + (size_t)r * NH * HD + c);
        v.x *= scale; v.y *= scale; v.z *= scale; v.w *= scale;
        *(float4*)(Qs + r * QPITCH + c) = v;
    }
    if (tid < FBR) { ms[tid] = -1e30f; ls[tid] = 0.f; }
    __syncthreads();

    // Convert Q fragments to registers once (reused every kt iteration).
    uint32_t qa[16][4];
    {
        const float* qsw = Qs + (wr * 16 + qr) * QPITCH;
#pragma unroll
        for (int kk = 0; kk < 16; ++kk) {
            const float* ap = qsw + kk * 8 + qc;
            qa[kk][0] = f2tf(ap[0]);
            qa[kk][1] = f2tf(ap[8 * QPITCH]);
            qa[kk][2] = f2tf(ap[4]);
            qa[kk][3] = f2tf(ap[8 * QPITCH + 4]);
        }
    }

    float o[8][4];
#pragma unroll
    for (int n = 0; n < 8; ++n)
#pragma unroll
        for (int i = 0; i < 4; ++i) o[n][i] = 0.f;

    const int row0 = wr * 16 + qr;

    for (int kt = 0; kt <= qt; ++kt) {
        __syncthreads();   // prior-iter reads of Kp/Vs/Ps complete

        const float* Kbase = Kg + ((size_t)(b * SEQ + kt * FBC) * NKV + kvh) * HD;
        const float* Vbase = Vg + ((size_t)(b * SEQ + kt * FBC) * NKV + kvh) * HD;

        // Fill Kp: token-major, d pair-packed: pairs (d, d+4) adjacent (fp32).
#pragma unroll
        for (int it = 0; it < 4; ++it) {
            int idx = it * 256 + tid;      // 0..1023
            int r = idx >> 4;              // token 0..63
            int c = (idx & 15) << 3;       // d group of 8
            const float* src = Kbase + (size_t)r * NKV * HD + c;
            float4 x0 = *(const float4*)(src);
            float4 x1 = *(const float4*)(src + 4);
            float* dst = Kp + r * KPITCH + c;
            *(float2*)(dst + 0) = make_float2(x0.x, x1.x);
            *(float2*)(dst + 2) = make_float2(x0.y, x1.y);
            *(float2*)(dst + 4) = make_float2(x0.z, x1.z);
            *(float2*)(dst + 6) = make_float2(x0.w, x1.w);
        }
        // Fill Vs: natural [token][d], float4 conflict-free.
#pragma unroll
        for (int it = 0; it < 8; ++it) {
            int idx = it * 256 + tid;
            int r = idx >> 5;
            int c = (idx & 31) << 2;
            *(float4*)(Vs + r * VPITCH + c) =
                *(const float4*)(Vbase + (size_t)r * NKV * HD + c);
        }
        __syncthreads();

        // --- S = Q @ K^T (warp: 16 rows x 32 cols); B frags = float2 from Kp ---
        float sacc[4][4];
#pragma unroll
        for (int n = 0; n < 4; ++n)
#pragma unroll
            for (int i = 0; i < 4; ++i) sacc[n][i] = 0.f;

#pragma unroll
        for (int kk = 0; kk < 16; ++kk) {
#pragma unroll
            for (int n = 0; n < 4; ++n) {
                const float* bp = Kp + (wc * 32 + n * 8 + qr) * KPITCH + kk * 8 + qc * 2;
                float2 bv = *(const float2*)bp;
                mma_tf32(sacc[n], qa[kk][0], qa[kk][1], qa[kk][2], qa[kk][3],
                         f2tf(bv.x), f2tf(bv.y));
            }
        }

        // Causal mask (original column indices) + store P pair-permuted.
        if (kt == qt) {
#pragma unroll
            for (int n = 0; n < 4; ++n) {
                int col = wc * 32 + n * 8 + qc * 2;
                if (col > row0)         sacc[n][0] = -1e30f;
                if (col + 1 > row0)     sacc[n][1] = -1e30f;
                if (col > row0 + 8)     sacc[n][2] = -1e30f;
                if (col + 1 > row0 + 8) sacc[n][3] = -1e30f;
            }
        }
        {
            int pc = (qc & 1) * 4 + (qc >> 1);   // permuted pos of col j=2*qc
#pragma unroll
            for (int n = 0; n < 4; ++n) {
                int pos = (wc * 4 + n) * 8 + pc;
                Ps[row0 * PPITCH + pos]           = sacc[n][0];
                Ps[row0 * PPITCH + pos + 2]       = sacc[n][1];
                Ps[(row0 + 8) * PPITCH + pos]     = sacc[n][2];
                Ps[(row0 + 8) * PPITCH + pos + 2] = sacc[n][3];
            }
        }
        __syncthreads();

        // --- online softmax: 4 threads per row, float4 vectorized ---
        {
            int row = tid >> 2;
            float* pr = Ps + row * PPITCH + (tid & 3) * 16;
            float4 p0 = *(float4*)(pr);
            float4 p1 = *(float4*)(pr + 4);
            float4 p2 = *(float4*)(pr + 8);
            float4 p3 = *(float4*)(pr + 12);
            float rmax = fmaxf(fmaxf(fmaxf(p0.x, p0.y), fmaxf(p0.z, p0.w)),
                               fmaxf(fmaxf(p1.x, p1.y), fmaxf(p1.z, p1.w)));
            rmax = fmaxf(rmax, fmaxf(fmaxf(fmaxf(p2.x, p2.y), fmaxf(p2.z, p2.w)),
                                     fmaxf(fmaxf(p3.x, p3.y), fmaxf(p3.z, p3.w))));
            rmax = fmaxf(rmax, __shfl_xor_sync(0xffffffffu, rmax, 1));
            rmax = fmaxf(rmax, __shfl_xor_sync(0xffffffffu, rmax, 2));

            float mold = ms[row];
            float mn = fmaxf(mold, rmax);
            p0.x = __expf(p0.x - mn); p0.y = __expf(p0.y - mn);
            p0.z = __expf(p0.z - mn); p0.w = __expf(p0.w - mn);
            p1.x = __expf(p1.x - mn); p1.y = __expf(p1.y - mn);
            p1.z = __expf(p1.z - mn); p1.w = __expf(p1.w - mn);
            p2.x = __expf(p2.x - mn); p2.y = __expf(p2.y - mn);
            p2.z = __expf(p2.z - mn); p2.w = __expf(p2.w - mn);
            p3.x = __expf(p3.x - mn); p3.y = __expf(p3.y - mn);
            p3.z = __expf(p3.z - mn); p3.w = __expf(p3.w - mn);
            *(float4*)(pr)      = p0;
            *(float4*)(pr + 4)  = p1;
            *(float4*)(pr + 8)  = p2;
            *(float4*)(pr + 12) = p3;
            float sum = (p0.x + p0.y + p0.z + p0.w) + (p1.x + p1.y + p1.z + p1.w)
                      + (p2.x + p2.y + p2.z + p2.w) + (p3.x + p3.y + p3.z + p3.w);
            sum += __shfl_xor_sync(0xffffffffu, sum, 1);
            sum += __shfl_xor_sync(0xffffffffu, sum, 2);

            if ((tid & 3) == 0) {
                float corr = __expf(mold - mn);
                ls[row] = ls[row] * corr + sum;
                ms[row] = mn;
                osc[row] = corr;
            }
        }
        __syncthreads();

        // --- rescale accumulator, O += P @ V ---
        {
            float c0 = osc[row0];
            float c1 = osc[row0 + 8];
#pragma unroll
            for (int n = 0; n < 8; ++n) {
                o[n][0] *= c0; o[n][1] *= c0;
                o[n][2] *= c1; o[n][3] *= c1;
            }
        }
#pragma unroll
        for (int kk = 0; kk < 8; ++kk) {
            const float* ap = Ps + row0 * PPITCH + kk * 8 + qc * 2;
            float2 av0 = *(const float2*)ap;
            float2 av1 = *(const float2*)(ap + 8 * PPITCH);
            uint32_t a0 = f2tf(av0.x);   // (row qr,   k)
            uint32_t a1 = f2tf(av1.x);   // (row qr+8, k)
            uint32_t a2 = f2tf(av0.y);   // (row qr,   k+4)
            uint32_t a3 = f2tf(av1.y);   // (row qr+8, k+4)
#pragma unroll
            for (int n = 0; n < 8; ++n) {
                const float* bp = Vs + (kk * 8 + qc) * VPITCH + wc * 64 + n * 8 + qr;
                uint32_t b0 = f2tf(bp[0]);
                uint32_t b1 = f2tf(bp[4 * VPITCH]);
                mma_tf32(o[n], a0, a1, a2, a3, b0, b1);
            }
        }
    }

    // Final 1/l normalization + store.
    float inv0 = 1.f / ls[row0];
    float inv1 = 1.f / ls[row0 + 8];
    int srow0 = b * SEQ + qt * FBR + row0;
#pragma unroll
    for (int n = 0; n < 8; ++n) {
        int col = wc * 64 + n * 8 + qc * 2;
        float* p0 = Og + ((size_t)srow0 * NH + qh) * HD + col;
        float* p1 = Og + ((size_t)(srow0 + 8) * NH + qh) * HD + col;
        *(float2*)p0 = make_float2(o[n][0] * inv0, o[n][1] * inv0);
        *(float2*)p1 = make_float2(o[n][2] * inv1, o[n][3] * inv1);
    }
}

// ---------------------------------------------------------------------------
// Launcher
// ---------------------------------------------------------------------------
extern "C" void kernel_launch(void* const* d_in, const int* in_sizes, int n_in,
                              void* d_out, int out_size)
{
    const float* x  = (const float*)d_in[0];
    const float* wq = (const float*)d_in[1];
    const float* bq = (const float*)d_in[2];
    const float* wk = (const float*)d_in[3];
    const float* bk = (const float*)d_in[4];
    const float* wv = (const float*)d_in[5];
    const float* bv = (const float*)d_in[6];
    const float* wo = (const float*)d_in[7];
    const float* bo = (const float*)d_in[8];
    float* out = (float*)d_out;

    float *q, *k, *v, *attn;
    __half *xh, *attnh, *wqh, *wkh, *wvh, *woh;
    cudaGetSymbolAddress((void**)&q,     g_q);
    cudaGetSymbolAddress((void**)&k,     g_k);
    cudaGetSymbolAddress((void**)&v,     g_v);
    cudaGetSymbolAddress((void**)&attn,  g_attn);
    cudaGetSymbolAddress((void**)&xh,    g_xh);
    cudaGetSymbolAddress((void**)&attnh, g_attnh);
    cudaGetSymbolAddress((void**)&wqh,   g_wqh);
    cudaGetSymbolAddress((void**)&wkh,   g_wkh);
    cudaGetSymbolAddress((void**)&wvh,   g_wvh);
    cudaGetSymbolAddress((void**)&woh,   g_woh);

    // fp16 pre-conversion: x elementwise; weights converted + transposed to [N][K]
    {
        int n4x = (MROWS * HIDK) / 4;
        cvt_h_kernel<<<(n4x + 255) / 256, 256>>>(x, xh, n4x);
        dim3 gtq((NH * HD) / 32, HIDK / 32);       // wq: [2048][2048] -> [2048][2048]
        cvt_h_transpose_kernel<<<gtq, 256>>>(wq, wqh, HIDK, NH * HD);
        dim3 gtk((NKV * HD) / 32, HIDK / 32);      // wk/wv: [2048][512] -> [512][2048]
        cvt_h_transpose_kernel<<<gtk, 256>>>(wk, wkh, HIDK, NKV * HD);
        cvt_h_transpose_kernel<<<gtk, 256>>>(wv, wvh, HIDK, NKV * HD);
        dim3 gto(HIDK / 32, HIDK / 32);            // wo: [2048][2048]
        cvt_h_transpose_kernel<<<gto, 256>>>(wo, woh, HIDK, HIDK);
    }

    const int hgemm_smem = 2 * 128 * (HPA + HPB) * (int)sizeof(__half);  // 40960
    cudaFuncSetAttribute(h_gemm_bias,
                         cudaFuncAttributeMaxDynamicSharedMemorySize, hgemm_smem);

    // Projections (fp16 inputs, fp32 accumulate)
    {
        dim3 gq_(HIDK / 128, MROWS / 128);
        h_gemm_bias<<<gq_, 256, hgemm_smem>>>(xh, wqh, bq, q, MROWS, NH * HD, HIDK);
        dim3 gk_((NKV * HD) / 128, MROWS / 128);
        h_gemm_bias<<<gk_, 256, hgemm_smem>>>(xh, wkh, bk, k, MROWS, NKV * HD, HIDK);
        h_gemm_bias<<<gk_, 256, hgemm_smem>>>(xh, wvh, bv, v, MROWS, NKV * HD, HIDK);
    }

    // Attention (frozen R12 kernel, fp32 in/out)
    {
        const int fl_smem = (FBR * QPITCH + FBC * KPITCH + FBC * VPITCH
                             + FBR * PPITCH + 3 * FBR) * sizeof(float);
        cudaFuncSetAttribute(flash_attn_tf32_kernel,
                             cudaFuncAttributeMaxDynamicSharedMemorySize, fl_smem);
        dim3 ga(SEQ / FBR, NH, BATCH);
        flash_attn_tf32_kernel<<<ga, 256, fl_smem>>>(q, k, v, attn);
    }

    // attn -> fp16, then output projection
    {
        int n4a = (MROWS * HIDK) / 4;
        cvt_h_kernel<<<(n4a + 255) / 256, 256>>>(attn, attnh, n4a);
        dim3 go(HIDK / 128, MROWS / 128);
        h_gemm_bias<<<go, 256, hgemm_smem>>>(attnh, woh, bo, out, MROWS, HIDK, HIDK);
    }
}

// round 15
// speedup vs baseline: 2.6722x; 1.3746x over previous
#include <cuda_runtime.h>
#include <cuda_fp16.h>
#include <math.h>
#include <stdint.h>

// Problem constants
#define HIDK   2048
#define NH     16
#define NKV    4
#define HD     128
#define BATCH  2
#define SEQ    2048
#define MROWS  (BATCH * SEQ)     // 4096

// Scratch (device globals; no allocation allowed)
__device__ float  g_q[(size_t)MROWS * NH * HD];
__device__ float  g_k[(size_t)MROWS * NKV * HD];
__device__ float  g_v[(size_t)MROWS * NKV * HD];
__device__ float  g_attn[(size_t)MROWS * NH * HD];
// fp16 operands for the GEMMs
__device__ __half g_xh[(size_t)MROWS * HIDK];
__device__ __half g_attnh[(size_t)MROWS * HIDK];
__device__ __half g_wqh[(size_t)(NH * HD) * HIDK];    // transposed [N][K]
__device__ __half g_wkh[(size_t)(NKV * HD) * HIDK];   // transposed
__device__ __half g_wvh[(size_t)(NKV * HD) * HIDK];   // transposed
__device__ __half g_woh[(size_t)HIDK * HIDK];         // transposed

// ---------------------------------------------------------------------------
// Common PTX helpers
// ---------------------------------------------------------------------------
__device__ __forceinline__ void mma_f16(float c[4],
                                        uint32_t a0, uint32_t a1, uint32_t a2, uint32_t a3,
                                        uint32_t b0, uint32_t b1) {
    asm volatile(
        "mma.sync.aligned.m16n8k16.row.col.f32.f16.f16.f32 "
        "{%0,%1,%2,%3}, {%4,%5,%6,%7}, {%8,%9}, {%0,%1,%2,%3};"
        : "+f"(c[0]), "+f"(c[1]), "+f"(c[2]), "+f"(c[3])
        : "r"(a0), "r"(a1), "r"(a2), "r"(a3), "r"(b0), "r"(b1));
}

__device__ __forceinline__ uint32_t smaddr(const void* p) {
    return (uint32_t)__cvta_generic_to_shared(p);
}

__device__ __forceinline__ uint32_t h2u(__half2 h) {
    return *reinterpret_cast<uint32_t*>(&h);
}

#define CPA16(dst, src) asm volatile("cp.async.cg.shared.global [%0], [%1], 16;\n" :: "r"(dst), "l"(src))
#define CPCOMMIT()      asm volatile("cp.async.commit_group;\n")
#define CPWAIT1()       asm volatile("cp.async.wait_group 1;\n" ::: "memory")
#define CPWAIT0()       asm volatile("cp.async.wait_group 0;\n" ::: "memory")

// ---------------------------------------------------------------------------
// fp32 -> fp16 elementwise convert (for A operands: x, attn)
// ---------------------------------------------------------------------------
__global__ __launch_bounds__(256)
void cvt_h_kernel(const float* __restrict__ in, __half* __restrict__ out, int n4)
{
    int i = blockIdx.x * 256 + threadIdx.x;
    if (i < n4) {
        float4 v = ((const float4*)in)[i];
        __half2 h0 = __floats2half2_rn(v.x, v.y);
        __half2 h1 = __floats2half2_rn(v.z, v.w);
        uint2 o;
        o.x = h2u(h0);
        o.y = h2u(h1);
        ((uint2*)out)[i] = o;
    }
}

// ---------------------------------------------------------------------------
// fp32 [K][N] -> fp16 transposed [N][K] (for weights)
// ---------------------------------------------------------------------------
__global__ __launch_bounds__(256)
void cvt_h_transpose_kernel(const float* __restrict__ in, __half* __restrict__ out,
                            int K, int N)
{
    __shared__ float t[32][33];
    int nb = blockIdx.x * 32;
    int kb = blockIdx.y * 32;
    int tx = threadIdx.x & 31;
    int ty = threadIdx.x >> 5;     // 0..7
#pragma unroll
    for (int i = 0; i < 4; ++i)
        t[ty + i * 8][tx] = in[(size_t)(kb + ty + i * 8) * N + nb + tx];
    __syncthreads();
#pragma unroll
    for (int i = 0; i < 4; ++i)
        out[(size_t)(nb + ty + i * 8) * K + kb + tx] = __float2half_rn(t[tx][ty + i * 8]);
}

// ---------------------------------------------------------------------------
// FP16 tensor-core GEMM (R14 verbatim): C = A[M,K] @ Bt[N,K]^T + bias
// ---------------------------------------------------------------------------
#define HPA 40
#define HPB 40

__global__ __launch_bounds__(256, 2)
void h_gemm_bias(const __half* __restrict__ A,
                 const __half* __restrict__ Bt,
                 const float* __restrict__ bias,
                 float* __restrict__ C,
                 int M, int N, int K)
{
    extern __shared__ __half hsm[];
    __half* As = hsm;
    __half* Bs = hsm + 2 * 128 * HPA;

    const int tid  = threadIdx.x;
    const int lane = tid & 31;
    const int warp = tid >> 5;
    const int wr = warp & 3;
    const int wc = warp >> 2;
    const int qr = lane >> 2;
    const int qc = lane & 3;
    const int rowBase = blockIdx.y * 128;
    const int colBase = blockIdx.x * 128;

    float acc[2][8][4];
#pragma unroll
    for (int m = 0; m < 2; ++m)
#pragma unroll
        for (int n = 0; n < 8; ++n)
#pragma unroll
            for (int i = 0; i < 4; ++i) acc[m][n][i] = 0.f;

    const int steps = K >> 5;

    {
        __half* as = As;
        __half* bs = Bs;
#pragma unroll
        for (int it = 0; it < 2; ++it) {
            int idx = it * 256 + tid;
            int r = idx >> 2;
            int c = (idx & 3) << 3;
            CPA16(smaddr(as + r * HPA + c), A + (size_t)(rowBase + r) * K + c);
            CPA16(smaddr(bs + r * HPB + c), Bt + (size_t)(colBase + r) * K + c);
        }
        CPCOMMIT();
    }

    for (int s = 0; s < steps; ++s) {
        if (s + 1 < steps) {
            int k0 = (s + 1) << 5;
            __half* as = As + ((s + 1) & 1) * 128 * HPA;
            __half* bs = Bs + ((s + 1) & 1) * 128 * HPB;
#pragma unroll
            for (int it = 0; it < 2; ++it) {
                int idx = it * 256 + tid;
                int r = idx >> 2;
                int c = (idx & 3) << 3;
                CPA16(smaddr(as + r * HPA + c), A + (size_t)(rowBase + r) * K + k0 + c);
                CPA16(smaddr(bs + r * HPB + c), Bt + (size_t)(colBase + r) * K + k0 + c);
            }
            CPCOMMIT();
            CPWAIT1();
        } else {
            CPWAIT0();
        }
        __syncthreads();

        const __half* as = As + (s & 1) * 128 * HPA + (wr * 32) * HPA;
        const __half* bs = Bs + (s & 1) * 128 * HPB + (wc * 64) * HPB;

#pragma unroll
        for (int kk = 0; kk < 2; ++kk) {
            uint32_t af[2][4];
#pragma unroll
            for (int m = 0; m < 2; ++m) {
                const __half* ap = as + (m * 16 + qr) * HPA + kk * 16 + qc * 2;
                af[m][0] = *(const uint32_t*)(ap);
                af[m][1] = *(const uint32_t*)(ap + 8 * HPA);
                af[m][2] = *(const uint32_t*)(ap + 8);
                af[m][3] = *(const uint32_t*)(ap + 8 * HPA + 8);
            }
#pragma unroll
            for (int n = 0; n < 8; ++n) {
                const __half* bp = bs + (n * 8 + qr) * HPB + kk * 16 + qc * 2;
                uint32_t b0 = *(const uint32_t*)(bp);
                uint32_t b1 = *(const uint32_t*)(bp + 8);
                mma_f16(acc[0][n], af[0][0], af[0][1], af[0][2], af[0][3], b0, b1);
                mma_f16(acc[1][n], af[1][0], af[1][1], af[1][2], af[1][3], b0, b1);
            }
        }
        __syncthreads();
    }

#pragma unroll
    for (int m = 0; m < 2; ++m) {
        int row = rowBase + wr * 32 + m * 16 + qr;
#pragma unroll
        for (int n = 0; n < 8; ++n) {
            int col = colBase + wc * 64 + n * 8 + qc * 2;
            float bx = bias[col], by = bias[col + 1];
            float2 v0 = make_float2(acc[m][n][0] + bx, acc[m][n][1] + by);
            float2 v1 = make_float2(acc[m][n][2] + bx, acc[m][n][3] + by);
            *(float2*)(C + (size_t)row * N + col)       = v0;
            *(float2*)(C + (size_t)(row + 8) * N + col) = v1;
        }
    }
}

// ---------------------------------------------------------------------------
// Flash attention v-fp16: R12 structure, fp16 operands, m16n8k16.
//   Qh/Kh: fp16 natural row-major, pitch 136 halves (68 words ≡ 4 mod 32)
//   Vh:    half2 token-pair words (t, t+4), [32 pairs][136 words] (≡8 mod 32)
//   Ps:    fp32 permuted (R12 verbatim) for masked softmax
//   Ph:    fp16 permuted P written by softmax post-exp, pitch 72 halves
//   Q cache: qa[8][4] = 32 regs; smem 79.6 KB.
// ---------------------------------------------------------------------------
#define FBR 64
#define FBC 64
#define FQP 136   // halves
#define FKP 136   // halves
#define FVP 136   // words
#define FPS 68    // floats
#define FPH 72    // halves

__global__ __launch_bounds__(256)
void flash_attn_f16_kernel(const float* __restrict__ Q,
                           const float* __restrict__ Kg,
                           const float* __restrict__ Vg,
                           float* __restrict__ Og)
{
    extern __shared__ float sm[];
    __half*    Qh = (__half*)sm;                 // [64][136] halves  (4352 f)
    __half*    Kh = (__half*)(sm + 4352);        // [64][136] halves  (4352 f)
    uint32_t*  Vh = (uint32_t*)(sm + 8704);      // [32][136] words   (4352 f)
    float*     Ps = sm + 13056;                  // [64][68] fp32     (4352 f)
    __half*    Ph = (__half*)(sm + 17408);       // [64][72] halves   (2304 f)
    float*     ms  = sm + 19712;
    float*     ls  = ms + FBR;
    float*     osc = ls + FBR;

    const int tid  = threadIdx.x;
    const int lane = tid & 31;
    const int warp = tid >> 5;
    const int wr = warp & 3;                // 4 warp rows x 16
    const int wc = warp >> 2;               // 2 warp cols
    const int qr = lane >> 2;
    const int qc = lane & 3;

    const int qt  = blockIdx.x;
    const int qh  = blockIdx.y;
    const int b   = blockIdx.z;
    const int kvh = qh >> 2;

    const float scale = 0.08838834764831845f; // 1/sqrt(128)
    const int row0 = wr * 16 + qr;

    // --- Q fill: fp32 -> fp16 pre-scaled; uint4 stores (8 halves) ---
    const float* Qbase = Q + ((size_t)(b * SEQ + qt * FBR) * NH + qh) * HD;
#pragma unroll
    for (int it = 0; it < 4; ++it) {
        int idx = it * 256 + tid;          // 0..1023
        int r = idx >> 4;                  // row 0..63
        int c = (idx & 15) << 3;           // d octet
        const float* src = Qbase + (size_t)r * NH * HD + c;
        float4 x0 = *(const float4*)(src);
        float4 x1 = *(const float4*)(src + 4);
        uint4 o;
        o.x = h2u(__floats2half2_rn(x0.x * scale, x0.y * scale));
        o.y = h2u(__floats2half2_rn(x0.z * scale, x0.w * scale));
        o.z = h2u(__floats2half2_rn(x1.x * scale, x1.y * scale));
        o.w = h2u(__floats2half2_rn(x1.z * scale, x1.w * scale));
        *(uint4*)(Qh + r * FQP + c) = o;
    }
    if (tid < FBR) { ms[tid] = -1e30f; ls[tid] = 0.f; }
    __syncthreads();

    // --- Q register cache (built once): qa[8][4] ---
    uint32_t qa[8][4];
#pragma unroll
    for (int kk = 0; kk < 8; ++kk) {
        const __half* qp = Qh + row0 * FQP + kk * 16 + qc * 2;
        qa[kk][0] = *(const uint32_t*)(qp);
        qa[kk][1] = *(const uint32_t*)(qp + 8 * FQP);
        qa[kk][2] = *(const uint32_t*)(qp + 8);
        qa[kk][3] = *(const uint32_t*)(qp + 8 * FQP + 8);
    }

    float o[8][4];
#pragma unroll
    for (int n = 0; n < 8; ++n)
#pragma unroll
        for (int i = 0; i < 4; ++i) o[n][i] = 0.f;

    for (int kt = 0; kt <= qt; ++kt) {
        __syncthreads();   // prior-iter reads complete before refill

        const float* Kbase = Kg + ((size_t)(b * SEQ + kt * FBC) * NKV + kvh) * HD;
        const float* Vbase = Vg + ((size_t)(b * SEQ + kt * FBC) * NKV + kvh) * HD;

        // K fill: fp16 natural row-major.
#pragma unroll
        for (int it = 0; it < 4; ++it) {
            int idx = it * 256 + tid;
            int r = idx >> 4;
            int c = (idx & 15) << 3;
            const float* src = Kbase + (size_t)r * NKV * HD + c;
            float4 x0 = *(const float4*)(src);
            float4 x1 = *(const float4*)(src + 4);
            uint4 oo;
            oo.x = h2u(__floats2half2_rn(x0.x, x0.y));
            oo.y = h2u(__floats2half2_rn(x0.z, x0.w));
            oo.z = h2u(__floats2half2_rn(x1.x, x1.y));
            oo.w = h2u(__floats2half2_rn(x1.z, x1.w));
            *(uint4*)(Kh + r * FKP + c) = oo;
        }
        // V fill: token-pair (t, t+4) half2 words. pair pr = g*4+qc_p,
        // tokens t = g*8+qc_p and t+4. Coalesced LDGs, conflict-free STS.128.
#pragma unroll
        for (int it = 0; it < 4; ++it) {
            int idx = it * 256 + tid;          // 0..1023
            int pr = idx >> 5;                 // pair row 0..31 (warp-uniform)
            int c = (idx & 31) << 2;           // d base (lane*4)
            int t = ((pr >> 2) << 3) + (pr & 3);
            const float* s0 = Vbase + (size_t)t * NKV * HD + c;
            const float* s1 = Vbase + (size_t)(t + 4) * NKV * HD + c;
            float4 v0 = *(const float4*)s0;
            float4 v1 = *(const float4*)s1;
            uint4 oo;
            oo.x = h2u(__floats2half2_rn(v0.x, v1.x));
            oo.y = h2u(__floats2half2_rn(v0.y, v1.y));
            oo.z = h2u(__floats2half2_rn(v0.z, v1.z));
            oo.w = h2u(__floats2half2_rn(v0.w, v1.w));
            *(uint4*)(Vh + pr * FVP + c) = oo;
        }
        __syncthreads();

        // --- S = Q @ K^T (warp: 16 rows x 32 cols), m16n8k16 ---
        float sacc[4][4];
#pragma unroll
        for (int n = 0; n < 4; ++n)
#pragma unroll
            for (int i = 0; i < 4; ++i) sacc[n][i] = 0.f;

#pragma unroll
        for (int kk = 0; kk < 8; ++kk) {
#pragma unroll
            for (int n = 0; n < 4; ++n) {
                const __half* kp = Kh + (wc * 32 + n * 8 + qr) * FKP + kk * 16 + qc * 2;
                uint32_t b0 = *(const uint32_t*)(kp);
                uint32_t b1 = *(const uint32_t*)(kp + 8);
                mma_f16(sacc[n], qa[kk][0], qa[kk][1], qa[kk][2], qa[kk][3], b0, b1);
            }
        }

        // Causal mask (diagonal tile) + store P pair-permuted to fp32 Ps.
        if (kt == qt) {
#pragma unroll
            for (int n = 0; n < 4; ++n) {
                int col = wc * 32 + n * 8 + qc * 2;
                if (col > row0)         sacc[n][0] = -1e30f;
                if (col + 1 > row0)     sacc[n][1] = -1e30f;
                if (col > row0 + 8)     sacc[n][2] = -1e30f;
                if (col + 1 > row0 + 8) sacc[n][3] = -1e30f;
            }
        }
        {
            int pc = (qc & 1) * 4 + (qc >> 1);
#pragma unroll
            for (int n = 0; n < 4; ++n) {
                int pos = (wc * 4 + n) * 8 + pc;
                Ps[row0 * FPS + pos]           = sacc[n][0];
                Ps[row0 * FPS + pos + 2]       = sacc[n][1];
                Ps[(row0 + 8) * FPS + pos]     = sacc[n][2];
                Ps[(row0 + 8) * FPS + pos + 2] = sacc[n][3];
            }
        }
        __syncthreads();

        // --- online softmax: fp32 in, writes fp16 Ph (post-exp) ---
        {
            int row = tid >> 2;
            float* pr = Ps + row * FPS + (tid & 3) * 16;
            float4 p0 = *(float4*)(pr);
            float4 p1 = *(float4*)(pr + 4);
            float4 p2 = *(float4*)(pr + 8);
            float4 p3 = *(float4*)(pr + 12);
            float rmax = fmaxf(fmaxf(fmaxf(p0.x, p0.y), fmaxf(p0.z, p0.w)),
                               fmaxf(fmaxf(p1.x, p1.y), fmaxf(p1.z, p1.w)));
            rmax = fmaxf(rmax, fmaxf(fmaxf(fmaxf(p2.x, p2.y), fmaxf(p2.z, p2.w)),
                                     fmaxf(fmaxf(p3.x, p3.y), fmaxf(p3.z, p3.w))));
            rmax = fmaxf(rmax, __shfl_xor_sync(0xffffffffu, rmax, 1));
            rmax = fmaxf(rmax, __shfl_xor_sync(0xffffffffu, rmax, 2));

            float mold = ms[row];
            float mn = fmaxf(mold, rmax);
            p0.x = __expf(p0.x - mn); p0.y = __expf(p0.y - mn);
            p0.z = __expf(p0.z - mn); p0.w = __expf(p0.w - mn);
            p1.x = __expf(p1.x - mn); p1.y = __expf(p1.y - mn);
            p1.z = __expf(p1.z - mn); p1.w = __expf(p1.w - mn);
            p2.x = __expf(p2.x - mn); p2.y = __expf(p2.y - mn);
            p2.z = __expf(p2.z - mn); p2.w = __expf(p2.w - mn);
            p3.x = __expf(p3.x - mn); p3.y = __expf(p3.y - mn);
            p3.z = __expf(p3.z - mn); p3.w = __expf(p3.w - mn);

            uint32_t* php = (uint32_t*)(Ph + row * FPH) + (tid & 3) * 8;
            php[0] = h2u(__floats2half2_rn(p0.x, p0.y));
            php[1] = h2u(__floats2half2_rn(p0.z, p0.w));
            php[2] = h2u(__floats2half2_rn(p1.x, p1.y));
            php[3] = h2u(__floats2half2_rn(p1.z, p1.w));
            php[4] = h2u(__floats2half2_rn(p2.x, p2.y));
            php[5] = h2u(__floats2half2_rn(p2.z, p2.w));
            php[6] = h2u(__floats2half2_rn(p3.x, p3.y));
            php[7] = h2u(__floats2half2_rn(p3.z, p3.w));

            float sum = (p0.x + p0.y + p0.z + p0.w) + (p1.x + p1.y + p1.z + p1.w)
                      + (p2.x + p2.y + p2.z + p2.w) + (p3.x + p3.y + p3.z + p3.w);
            sum += __shfl_xor_sync(0xffffffffu, sum, 1);
            sum += __shfl_xor_sync(0xffffffffu, sum, 2);

            if ((tid & 3) == 0) {
                float corr = __expf(mold - mn);
                ls[row] = ls[row] * corr + sum;
                ms[row] = mn;
                osc[row] = corr;
            }
        }
        __syncthreads();

        // --- rescale accumulator, O += P @ V (m16n8k16, permuted k) ---
        {
            float c0 = osc[row0];
            float c1 = osc[row0 + 8];
#pragma unroll
            for (int n = 0; n < 8; ++n) {
                o[n][0] *= c0; o[n][1] *= c0;
                o[n][2] *= c1; o[n][3] *= c1;
            }
        }
#pragma unroll
        for (int kk = 0; kk < 4; ++kk) {
            const __half* pp = Ph + row0 * FPH + kk * 16 + qc * 2;
            uint32_t a0 = *(const uint32_t*)(pp);
            uint32_t a1 = *(const uint32_t*)(pp + 8 * FPH);
            uint32_t a2 = *(const uint32_t*)(pp + 8);
            uint32_t a3 = *(const uint32_t*)(pp + 8 * FPH + 8);
#pragma unroll
            for (int n = 0; n < 8; ++n) {
                int d = wc * 64 + n * 8 + qr;
                uint32_t b0 = Vh[(8 * kk + qc) * FVP + d];
                uint32_t b1 = Vh[(8 * kk + 4 + qc) * FVP + d];
                mma_f16(o[n], a0, a1, a2, a3, b0, b1);
            }
        }
    }

    // Final 1/l normalization + store.
    float inv0 = 1.f / ls[row0];
    float inv1 = 1.f / ls[row0 + 8];
    int srow0 = b * SEQ + qt * FBR + row0;
#pragma unroll
    for (int n = 0; n < 8; ++n) {
        int col = wc * 64 + n * 8 + qc * 2;
        float* p0 = Og + ((size_t)srow0 * NH + qh) * HD + col;
        float* p1 = Og + ((size_t)(srow0 + 8) * NH + qh) * HD + col;
        *(float2*)p0 = make_float2(o[n][0] * inv0, o[n][1] * inv0);
        *(float2*)p1 = make_float2(o[n][2] * inv1, o[n][3] * inv1);
    }
}

// ---------------------------------------------------------------------------
// Launcher
// ---------------------------------------------------------------------------
extern "C" void kernel_launch(void* const* d_in, const int* in_sizes, int n_in,
                              void* d_out, int out_size)
{
    const float* x  = (const float*)d_in[0];
    const float* wq = (const float*)d_in[1];
    const float* bq = (const float*)d_in[2];
    const float* wk = (const float*)d_in[3];
    const float* bk = (const float*)d_in[4];
    const float* wv = (const float*)d_in[5];
    const float* bv = (const float*)d_in[6];
    const float* wo = (const float*)d_in[7];
    const float* bo = (const float*)d_in[8];
    float* out = (float*)d_out;

    float *q, *k, *v, *attn;
    __half *xh, *attnh, *wqh, *wkh, *wvh, *woh;
    cudaGetSymbolAddress((void**)&q,     g_q);
    cudaGetSymbolAddress((void**)&k,     g_k);
    cudaGetSymbolAddress((void**)&v,     g_v);
    cudaGetSymbolAddress((void**)&attn,  g_attn);
    cudaGetSymbolAddress((void**)&xh,    g_xh);
    cudaGetSymbolAddress((void**)&attnh, g_attnh);
    cudaGetSymbolAddress((void**)&wqh,   g_wqh);
    cudaGetSymbolAddress((void**)&wkh,   g_wkh);
    cudaGetSymbolAddress((void**)&wvh,   g_wvh);
    cudaGetSymbolAddress((void**)&woh,   g_woh);

    // fp16 pre-conversion: x elementwise; weights converted + transposed
    {
        int n4x = (MROWS * HIDK) / 4;
        cvt_h_kernel<<<(n4x + 255) / 256, 256>>>(x, xh, n4x);
        dim3 gtq((NH * HD) / 32, HIDK / 32);
        cvt_h_transpose_kernel<<<gtq, 256>>>(wq, wqh, HIDK, NH * HD);
        dim3 gtk((NKV * HD) / 32, HIDK / 32);
        cvt_h_transpose_kernel<<<gtk, 256>>>(wk, wkh, HIDK, NKV * HD);
        cvt_h_transpose_kernel<<<gtk, 256>>>(wv, wvh, HIDK, NKV * HD);
        dim3 gto(HIDK / 32, HIDK / 32);
        cvt_h_transpose_kernel<<<gto, 256>>>(wo, woh, HIDK, HIDK);
    }

    const int hgemm_smem = 2 * 128 * (HPA + HPB) * (int)sizeof(__half);  // 40960
    cudaFuncSetAttribute(h_gemm_bias,
                         cudaFuncAttributeMaxDynamicSharedMemorySize, hgemm_smem);

    // Projections (fp16 inputs, fp32 accumulate)
    {
        dim3 gq_(HIDK / 128, MROWS / 128);
        h_gemm_bias<<<gq_, 256, hgemm_smem>>>(xh, wqh, bq, q, MROWS, NH * HD, HIDK);
        dim3 gk_((NKV * HD) / 128, MROWS / 128);
        h_gemm_bias<<<gk_, 256, hgemm_smem>>>(xh, wkh, bk, k, MROWS, NKV * HD, HIDK);
        h_gemm_bias<<<gk_, 256, hgemm_smem>>>(xh, wvh, bv, v, MROWS, NKV * HD, HIDK);
    }

    // Attention (fp16 mma flash)
    {
        const int fl_smem = 19904 * (int)sizeof(float);   // 79616 bytes
        cudaFuncSetAttribute(flash_attn_f16_kernel,
                             cudaFuncAttributeMaxDynamicSharedMemorySize, fl_smem);
        dim3 ga(SEQ / FBR, NH, BATCH);
        flash_attn_f16_kernel<<<ga, 256, fl_smem>>>(q, k, v, attn);
    }

    // attn -> fp16, then output projection
    {
        int n4a = (MROWS * HIDK) / 4;
        cvt_h_kernel<<<(n4a + 255) / 256, 256>>>(attn, attnh, n4a);
        dim3 go(HIDK / 128, MROWS / 128);
        h_gemm_bias<<<go, 256, hgemm_smem>>>(attnh, woh, bo, out, MROWS, HIDK, HIDK);
    }
}

// round 16
// speedup vs baseline: 2.8703x; 1.0741x over previous
#include <cuda_runtime.h>
#include <cuda_fp16.h>
#include <math.h>
#include <stdint.h>

// Problem constants
#define HIDK   2048
#define NH     16
#define NKV    4
#define HD     128
#define BATCH  2
#define SEQ    2048
#define MROWS  (BATCH * SEQ)     // 4096

// Scratch (device globals; no allocation allowed)
__device__ __half g_qh[(size_t)MROWS * NH * HD];      // fp16 q (pre-scaled)
__device__ __half g_kh[(size_t)MROWS * NKV * HD];     // fp16 k
__device__ __half g_vh[(size_t)MROWS * NKV * HD];     // fp16 v
__device__ __half g_attnh[(size_t)MROWS * HIDK];      // fp16 attention output
__device__ __half g_xh[(size_t)MROWS * HIDK];
__device__ __half g_wqh[(size_t)(NH * HD) * HIDK];    // transposed [N][K]
__device__ __half g_wkh[(size_t)(NKV * HD) * HIDK];   // transposed
__device__ __half g_wvh[(size_t)(NKV * HD) * HIDK];   // transposed
__device__ __half g_woh[(size_t)HIDK * HIDK];         // transposed

// ---------------------------------------------------------------------------
// Common PTX helpers
// ---------------------------------------------------------------------------
__device__ __forceinline__ void mma_f16(float c[4],
                                        uint32_t a0, uint32_t a1, uint32_t a2, uint32_t a3,
                                        uint32_t b0, uint32_t b1) {
    asm volatile(
        "mma.sync.aligned.m16n8k16.row.col.f32.f16.f16.f32 "
        "{%0,%1,%2,%3}, {%4,%5,%6,%7}, {%8,%9}, {%0,%1,%2,%3};"
        : "+f"(c[0]), "+f"(c[1]), "+f"(c[2]), "+f"(c[3])
        : "r"(a0), "r"(a1), "r"(a2), "r"(a3), "r"(b0), "r"(b1));
}

__device__ __forceinline__ uint32_t smaddr(const void* p) {
    return (uint32_t)__cvta_generic_to_shared(p);
}

__device__ __forceinline__ uint32_t h2u(__half2 h) {
    return *reinterpret_cast<uint32_t*>(&h);
}
__device__ __forceinline__ __half2 u2h(uint32_t u) {
    return *reinterpret_cast<__half2*>(&u);
}

#define CPA16(dst, src) asm volatile("cp.async.cg.shared.global [%0], [%1], 16;\n" :: "r"(dst), "l"(src))
#define CPCOMMIT()      asm volatile("cp.async.commit_group;\n")
#define CPWAIT1()       asm volatile("cp.async.wait_group 1;\n" ::: "memory")
#define CPWAIT0()       asm volatile("cp.async.wait_group 0;\n" ::: "memory")

// ---------------------------------------------------------------------------
// fp32 -> fp16 elementwise convert (for x)
// ---------------------------------------------------------------------------
__global__ __launch_bounds__(256)
void cvt_h_kernel(const float* __restrict__ in, __half* __restrict__ out, int n4)
{
    int i = blockIdx.x * 256 + threadIdx.x;
    if (i < n4) {
        float4 v = ((const float4*)in)[i];
        uint2 o;
        o.x = h2u(__floats2half2_rn(v.x, v.y));
        o.y = h2u(__floats2half2_rn(v.z, v.w));
        ((uint2*)out)[i] = o;
    }
}

// ---------------------------------------------------------------------------
// fp32 [K][N] -> fp16 transposed [N][K] (for weights)
// ---------------------------------------------------------------------------
__global__ __launch_bounds__(256)
void cvt_h_transpose_kernel(const float* __restrict__ in, __half* __restrict__ out,
                            int K, int N)
{
    __shared__ float t[32][33];
    int nb = blockIdx.x * 32;
    int kb = blockIdx.y * 32;
    int tx = threadIdx.x & 31;
    int ty = threadIdx.x >> 5;     // 0..7
#pragma unroll
    for (int i = 0; i < 4; ++i)
        t[ty + i * 8][tx] = in[(size_t)(kb + ty + i * 8) * N + nb + tx];
    __syncthreads();
#pragma unroll
    for (int i = 0; i < 4; ++i)
        out[(size_t)(nb + ty + i * 8) * K + kb + tx] = __float2half_rn(t[tx][ty + i * 8]);
}

// ---------------------------------------------------------------------------
// FP16 GEMM shared body: fragments + mma (R14/R15-validated shape)
// ---------------------------------------------------------------------------
#define HPA 40
#define HPB 40

#define HGEMM_BODY(A, Bt, M, N, K)                                               \
    extern __shared__ __half hsm[];                                              \
    __half* As = hsm;                                                            \
    __half* Bs = hsm + 2 * 128 * HPA;                                            \
    const int tid  = threadIdx.x;                                                \
    const int lane = tid & 31;                                                   \
    const int warp = tid >> 5;                                                   \
    const int wr = warp & 3;                                                     \
    const int wc = warp >> 2;                                                    \
    const int qr = lane >> 2;                                                    \
    const int qc = lane & 3;                                                     \
    const int rowBase = blockIdx.y * 128;                                        \
    const int colBase = blockIdx.x * 128;                                        \
    float acc[2][8][4];                                                          \
    _Pragma("unroll")                                                            \
    for (int m = 0; m < 2; ++m)                                                  \
        _Pragma("unroll")                                                        \
        for (int n = 0; n < 8; ++n)                                              \
            _Pragma("unroll")                                                    \
            for (int i = 0; i < 4; ++i) acc[m][n][i] = 0.f;                      \
    const int steps = K >> 5;                                                    \
    {                                                                            \
        __half* as = As;                                                         \
        __half* bs = Bs;                                                         \
        _Pragma("unroll")                                                        \
        for (int it = 0; it < 2; ++it) {                                         \
            int idx = it * 256 + tid;                                            \
            int r = idx >> 2;                                                    \
            int c = (idx & 3) << 3;                                              \
            CPA16(smaddr(as + r * HPA + c), A + (size_t)(rowBase + r) * K + c);  \
            CPA16(smaddr(bs + r * HPB + c), Bt + (size_t)(colBase + r) * K + c); \
        }                                                                        \
        CPCOMMIT();                                                              \
    }                                                                            \
    for (int s = 0; s < steps; ++s) {                                            \
        if (s + 1 < steps) {                                                     \
            int k0 = (s + 1) << 5;                                               \
            __half* as = As + ((s + 1) & 1) * 128 * HPA;                         \
            __half* bs = Bs + ((s + 1) & 1) * 128 * HPB;                         \
            _Pragma("unroll")                                                    \
            for (int it = 0; it < 2; ++it) {                                     \
                int idx = it * 256 + tid;                                        \
                int r = idx >> 2;                                                \
                int c = (idx & 3) << 3;                                          \
                CPA16(smaddr(as + r * HPA + c), A + (size_t)(rowBase + r) * K + k0 + c);  \
                CPA16(smaddr(bs + r * HPB + c), Bt + (size_t)(colBase + r) * K + k0 + c); \
            }                                                                    \
            CPCOMMIT();                                                          \
            CPWAIT1();                                                           \
        } else {                                                                 \
            CPWAIT0();                                                           \
        }                                                                        \
        __syncthreads();                                                         \
        const __half* as = As + (s & 1) * 128 * HPA + (wr * 32) * HPA;           \
        const __half* bs = Bs + (s & 1) * 128 * HPB + (wc * 64) * HPB;           \
        _Pragma("unroll")                                                        \
        for (int kk = 0; kk < 2; ++kk) {                                         \
            uint32_t af[2][4];                                                   \
            _Pragma("unroll")                                                    \
            for (int m = 0; m < 2; ++m) {                                        \
                const __half* ap = as + (m * 16 + qr) * HPA + kk * 16 + qc * 2;  \
                af[m][0] = *(const uint32_t*)(ap);                               \
                af[m][1] = *(const uint32_t*)(ap + 8 * HPA);                     \
                af[m][2] = *(const uint32_t*)(ap + 8);                           \
                af[m][3] = *(const uint32_t*)(ap + 8 * HPA + 8);                 \
            }                                                                    \
            _Pragma("unroll")                                                    \
            for (int n = 0; n < 8; ++n) {                                        \
                const __half* bp = bs + (n * 8 + qr) * HPB + kk * 16 + qc * 2;   \
                uint32_t b0 = *(const uint32_t*)(bp);                            \
                uint32_t b1 = *(const uint32_t*)(bp + 8);                        \
                mma_f16(acc[0][n], af[0][0], af[0][1], af[0][2], af[0][3], b0, b1); \
                mma_f16(acc[1][n], af[1][0], af[1][1], af[1][2], af[1][3], b0, b1); \
            }                                                                    \
        }                                                                        \
        __syncthreads();                                                         \
    }

// fp32-output variant (final projection)
__global__ __launch_bounds__(256, 2)
void h_gemm_bias(const __half* __restrict__ A,
                 const __half* __restrict__ Bt,
                 const float* __restrict__ bias,
                 float* __restrict__ C,
                 int M, int N, int K)
{
    HGEMM_BODY(A, Bt, M, N, K)
#pragma unroll
    for (int m = 0; m < 2; ++m) {
        int row = rowBase + wr * 32 + m * 16 + qr;
#pragma unroll
        for (int n = 0; n < 8; ++n) {
            int col = colBase + wc * 64 + n * 8 + qc * 2;
            float bx = bias[col], by = bias[col + 1];
            float2 v0 = make_float2(acc[m][n][0] + bx, acc[m][n][1] + by);
            float2 v1 = make_float2(acc[m][n][2] + bx, acc[m][n][3] + by);
            *(float2*)(C + (size_t)row * N + col)       = v0;
            *(float2*)(C + (size_t)(row + 8) * N + col) = v1;
        }
    }
}

// fp16-output variant with alpha scale (q/k/v projections)
__global__ __launch_bounds__(256, 2)
void h_gemm_bias_h(const __half* __restrict__ A,
                   const __half* __restrict__ Bt,
                   const float* __restrict__ bias,
                   __half* __restrict__ C,
                   int M, int N, int K, float alpha)
{
    HGEMM_BODY(A, Bt, M, N, K)
#pragma unroll
    for (int m = 0; m < 2; ++m) {
        int row = rowBase + wr * 32 + m * 16 + qr;
#pragma unroll
        for (int n = 0; n < 8; ++n) {
            int col = colBase + wc * 64 + n * 8 + qc * 2;
            float bx = bias[col], by = bias[col + 1];
            uint32_t w0 = h2u(__floats2half2_rn((acc[m][n][0] + bx) * alpha,
                                                (acc[m][n][1] + by) * alpha));
            uint32_t w1 = h2u(__floats2half2_rn((acc[m][n][2] + bx) * alpha,
                                                (acc[m][n][3] + by) * alpha));
            *(uint32_t*)(C + (size_t)row * N + col)       = w0;
            *(uint32_t*)(C + (size_t)(row + 8) * N + col) = w1;
        }
    }
}

// ---------------------------------------------------------------------------
// Flash attention fp16 (R15 core frozen; fills/outputs now pure fp16)
//   Qh/Kh: fp16 natural row-major, pitch 136 halves
//   Vh:    half2 token-pair words (t, t+4), [32 pairs][136 words]
//   Ps:    fp32 permuted for masked softmax; Ph: fp16 permuted post-exp
//   Output written directly as fp16 (attnh).
// ---------------------------------------------------------------------------
#define FBR 64
#define FBC 64
#define FQP 136   // halves
#define FKP 136   // halves
#define FVP 136   // words
#define FPS 68    // floats
#define FPH 72    // halves

__global__ __launch_bounds__(256)
void flash_attn_f16_kernel(const __half* __restrict__ Q,
                           const __half* __restrict__ Kg,
                           const __half* __restrict__ Vg,
                           __half* __restrict__ Og)
{
    extern __shared__ float sm[];
    __half*    Qh = (__half*)sm;                 // [64][136] halves  (4352 f)
    __half*    Kh = (__half*)(sm + 4352);        // [64][136] halves  (4352 f)
    uint32_t*  Vh = (uint32_t*)(sm + 8704);      // [32][136] words   (4352 f)
    float*     Ps = sm + 13056;                  // [64][68] fp32     (4352 f)
    __half*    Ph = (__half*)(sm + 17408);       // [64][72] halves   (2304 f)
    float*     ms  = sm + 19712;
    float*     ls  = ms + FBR;
    float*     osc = ls + FBR;

    const int tid  = threadIdx.x;
    const int lane = tid & 31;
    const int warp = tid >> 5;
    const int wr = warp & 3;                // 4 warp rows x 16
    const int wc = warp >> 2;               // 2 warp cols
    const int qr = lane >> 2;
    const int qc = lane & 3;

    const int qt  = blockIdx.x;
    const int qh  = blockIdx.y;
    const int b   = blockIdx.z;
    const int kvh = qh >> 2;

    const int row0 = wr * 16 + qr;

    // --- Q fill: straight fp16 copy (q is pre-scaled by the projection) ---
    const __half* Qbase = Q + ((size_t)(b * SEQ + qt * FBR) * NH + qh) * HD;
#pragma unroll
    for (int it = 0; it < 4; ++it) {
        int idx = it * 256 + tid;          // 0..1023
        int r = idx >> 4;                  // row 0..63
        int c = (idx & 15) << 3;           // d octet
        *(uint4*)(Qh + r * FQP + c) =
            *(const uint4*)(Qbase + (size_t)r * NH * HD + c);
    }
    if (tid < FBR) { ms[tid] = -1e30f; ls[tid] = 0.f; }
    __syncthreads();

    // --- Q register cache (built once): qa[8][4] ---
    uint32_t qa[8][4];
#pragma unroll
    for (int kk = 0; kk < 8; ++kk) {
        const __half* qp = Qh + row0 * FQP + kk * 16 + qc * 2;
        qa[kk][0] = *(const uint32_t*)(qp);
        qa[kk][1] = *(const uint32_t*)(qp + 8 * FQP);
        qa[kk][2] = *(const uint32_t*)(qp + 8);
        qa[kk][3] = *(const uint32_t*)(qp + 8 * FQP + 8);
    }

    float o[8][4];
#pragma unroll
    for (int n = 0; n < 8; ++n)
#pragma unroll
        for (int i = 0; i < 4; ++i) o[n][i] = 0.f;

    for (int kt = 0; kt <= qt; ++kt) {
        __syncthreads();   // prior-iter reads complete before refill

        const __half* Kbase = Kg + ((size_t)(b * SEQ + kt * FBC) * NKV + kvh) * HD;
        const __half* Vbase = Vg + ((size_t)(b * SEQ + kt * FBC) * NKV + kvh) * HD;

        // K fill: straight fp16 copy.
#pragma unroll
        for (int it = 0; it < 4; ++it) {
            int idx = it * 256 + tid;
            int r = idx >> 4;
            int c = (idx & 15) << 3;
            *(uint4*)(Kh + r * FKP + c) =
                *(const uint4*)(Kbase + (size_t)r * NKV * HD + c);
        }
        // V fill: token-pair (t, t+4) interleave via half2 shuffles.
#pragma unroll
        for (int it = 0; it < 4; ++it) {
            int idx = it * 256 + tid;          // 0..1023
            int pr = idx >> 5;                 // pair row 0..31 (warp-uniform)
            int d0 = (idx & 31) << 2;          // d base (lane*4)
            int t = ((pr >> 2) << 3) + (pr & 3);
            uint2 a = *(const uint2*)(Vbase + (size_t)t * NKV * HD + d0);
            uint2 bb = *(const uint2*)(Vbase + (size_t)(t + 4) * NKV * HD + d0);
            uint4 oo;
            oo.x = h2u(__lows2half2 (u2h(a.x), u2h(bb.x)));
            oo.y = h2u(__highs2half2(u2h(a.x), u2h(bb.x)));
            oo.z = h2u(__lows2half2 (u2h(a.y), u2h(bb.y)));
            oo.w = h2u(__highs2half2(u2h(a.y), u2h(bb.y)));
            *(uint4*)(Vh + pr * FVP + d0) = oo;
        }
        __syncthreads();

        // --- S = Q @ K^T (warp: 16 rows x 32 cols), m16n8k16 ---
        float sacc[4][4];
#pragma unroll
        for (int n = 0; n < 4; ++n)
#pragma unroll
            for (int i = 0; i < 4; ++i) sacc[n][i] = 0.f;

#pragma unroll
        for (int kk = 0; kk < 8; ++kk) {
#pragma unroll
            for (int n = 0; n < 4; ++n) {
                const __half* kp = Kh + (wc * 32 + n * 8 + qr) * FKP + kk * 16 + qc * 2;
                uint32_t b0 = *(const uint32_t*)(kp);
                uint32_t b1 = *(const uint32_t*)(kp + 8);
                mma_f16(sacc[n], qa[kk][0], qa[kk][1], qa[kk][2], qa[kk][3], b0, b1);
            }
        }

        // Causal mask (diagonal tile) + store P pair-permuted to fp32 Ps.
        if (kt == qt) {
#pragma unroll
            for (int n = 0; n < 4; ++n) {
                int col = wc * 32 + n * 8 + qc * 2;
                if (col > row0)         sacc[n][0] = -1e30f;
                if (col + 1 > row0)     sacc[n][1] = -1e30f;
                if (col > row0 + 8)     sacc[n][2] = -1e30f;
                if (col + 1 > row0 + 8) sacc[n][3] = -1e30f;
            }
        }
        {
            int pc = (qc & 1) * 4 + (qc >> 1);
#pragma unroll
            for (int n = 0; n < 4; ++n) {
                int pos = (wc * 4 + n) * 8 + pc;
                Ps[row0 * FPS + pos]           = sacc[n][0];
                Ps[row0 * FPS + pos + 2]       = sacc[n][1];
                Ps[(row0 + 8) * FPS + pos]     = sacc[n][2];
                Ps[(row0 + 8) * FPS + pos + 2] = sacc[n][3];
            }
        }
        __syncthreads();

        // --- online softmax: fp32 in, writes fp16 Ph (post-exp) ---
        {
            int row = tid >> 2;
            float* pr = Ps + row * FPS + (tid & 3) * 16;
            float4 p0 = *(float4*)(pr);
            float4 p1 = *(float4*)(pr + 4);
            float4 p2 = *(float4*)(pr + 8);
            float4 p3 = *(float4*)(pr + 12);
            float rmax = fmaxf(fmaxf(fmaxf(p0.x, p0.y), fmaxf(p0.z, p0.w)),
                               fmaxf(fmaxf(p1.x, p1.y), fmaxf(p1.z, p1.w)));
            rmax = fmaxf(rmax, fmaxf(fmaxf(fmaxf(p2.x, p2.y), fmaxf(p2.z, p2.w)),
                                     fmaxf(fmaxf(p3.x, p3.y), fmaxf(p3.z, p3.w))));
            rmax = fmaxf(rmax, __shfl_xor_sync(0xffffffffu, rmax, 1));
            rmax = fmaxf(rmax, __shfl_xor_sync(0xffffffffu, rmax, 2));

            float mold = ms[row];
            float mn = fmaxf(mold, rmax);
            p0.x = __expf(p0.x - mn); p0.y = __expf(p0.y - mn);
            p0.z = __expf(p0.z - mn); p0.w = __expf(p0.w - mn);
            p1.x = __expf(p1.x - mn); p1.y = __expf(p1.y - mn);
            p1.z = __expf(p1.z - mn); p1.w = __expf(p1.w - mn);
            p2.x = __expf(p2.x - mn); p2.y = __expf(p2.y - mn);
            p2.z = __expf(p2.z - mn); p2.w = __expf(p2.w - mn);
            p3.x = __expf(p3.x - mn); p3.y = __expf(p3.y - mn);
            p3.z = __expf(p3.z - mn); p3.w = __expf(p3.w - mn);

            uint32_t* php = (uint32_t*)(Ph + row * FPH) + (tid & 3) * 8;
            php[0] = h2u(__floats2half2_rn(p0.x, p0.y));
            php[1] = h2u(__floats2half2_rn(p0.z, p0.w));
            php[2] = h2u(__floats2half2_rn(p1.x, p1.y));
            php[3] = h2u(__floats2half2_rn(p1.z, p1.w));
            php[4] = h2u(__floats2half2_rn(p2.x, p2.y));
            php[5] = h2u(__floats2half2_rn(p2.z, p2.w));
            php[6] = h2u(__floats2half2_rn(p3.x, p3.y));
            php[7] = h2u(__floats2half2_rn(p3.z, p3.w));

            float sum = (p0.x + p0.y + p0.z + p0.w) + (p1.x + p1.y + p1.z + p1.w)
                      + (p2.x + p2.y + p2.z + p2.w) + (p3.x + p3.y + p3.z + p3.w);
            sum += __shfl_xor_sync(0xffffffffu, sum, 1);
            sum += __shfl_xor_sync(0xffffffffu, sum, 2);

            if ((tid & 3) == 0) {
                float corr = __expf(mold - mn);
                ls[row] = ls[row] * corr + sum;
                ms[row] = mn;
                osc[row] = corr;
            }
        }
        __syncthreads();

        // --- rescale accumulator, O += P @ V (m16n8k16, permuted k) ---
        {
            float c0 = osc[row0];
            float c1 = osc[row0 + 8];
#pragma unroll
            for (int n = 0; n < 8; ++n) {
                o[n][0] *= c0; o[n][1] *= c0;
                o[n][2] *= c1; o[n][3] *= c1;
            }
        }
#pragma unroll
        for (int kk = 0; kk < 4; ++kk) {
            const __half* pp = Ph + row0 * FPH + kk * 16 + qc * 2;
            uint32_t a0 = *(const uint32_t*)(pp);
            uint32_t a1 = *(const uint32_t*)(pp + 8 * FPH);
            uint32_t a2 = *(const uint32_t*)(pp + 8);
            uint32_t a3 = *(const uint32_t*)(pp + 8 * FPH + 8);
#pragma unroll
            for (int n = 0; n < 8; ++n) {
                int d = wc * 64 + n * 8 + qr;
                uint32_t b0 = Vh[(8 * kk + qc) * FVP + d];
                uint32_t b1 = Vh[(8 * kk + 4 + qc) * FVP + d];
                mma_f16(o[n], a0, a1, a2, a3, b0, b1);
            }
        }
    }

    // Final 1/l normalization + fp16 store.
    float inv0 = 1.f / ls[row0];
    float inv1 = 1.f / ls[row0 + 8];
    int srow0 = b * SEQ + qt * FBR + row0;
#pragma unroll
    for (int n = 0; n < 8; ++n) {
        int col = wc * 64 + n * 8 + qc * 2;
        __half* p0 = Og + ((size_t)srow0 * NH + qh) * HD + col;
        __half* p1 = Og + ((size_t)(srow0 + 8) * NH + qh) * HD + col;
        *(uint32_t*)p0 = h2u(__floats2half2_rn(o[n][0] * inv0, o[n][1] * inv0));
        *(uint32_t*)p1 = h2u(__floats2half2_rn(o[n][2] * inv1, o[n][3] * inv1));
    }
}

// ---------------------------------------------------------------------------
// Launcher
// ---------------------------------------------------------------------------
extern "C" void kernel_launch(void* const* d_in, const int* in_sizes, int n_in,
                              void* d_out, int out_size)
{
    const float* x  = (const float*)d_in[0];
    const float* wq = (const float*)d_in[1];
    const float* bq = (const float*)d_in[2];
    const float* wk = (const float*)d_in[3];
    const float* bk = (const float*)d_in[4];
    const float* wv = (const float*)d_in[5];
    const float* bv = (const float*)d_in[6];
    const float* wo = (const float*)d_in[7];
    const float* bo = (const float*)d_in[8];
    float* out = (float*)d_out;

    __half *qh, *kh, *vh, *attnh, *xh, *wqh, *wkh, *wvh, *woh;
    cudaGetSymbolAddress((void**)&qh,    g_qh);
    cudaGetSymbolAddress((void**)&kh,    g_kh);
    cudaGetSymbolAddress((void**)&vh,    g_vh);
    cudaGetSymbolAddress((void**)&attnh, g_attnh);
    cudaGetSymbolAddress((void**)&xh,    g_xh);
    cudaGetSymbolAddress((void**)&wqh,   g_wqh);
    cudaGetSymbolAddress((void**)&wkh,   g_wkh);
    cudaGetSymbolAddress((void**)&wvh,   g_wvh);
    cudaGetSymbolAddress((void**)&woh,   g_woh);

    const float scale = 0.08838834764831845f;  // 1/sqrt(128)

    // fp16 pre-conversion: x elementwise; weights converted + transposed
    {
        int n4x = (MROWS * HIDK) / 4;
        cvt_h_kernel<<<(n4x + 255) / 256, 256>>>(x, xh, n4x);
        dim3 gtq((NH * HD) / 32, HIDK / 32);
        cvt_h_transpose_kernel<<<gtq, 256>>>(wq, wqh, HIDK, NH * HD);
        dim3 gtk((NKV * HD) / 32, HIDK / 32);
        cvt_h_transpose_kernel<<<gtk, 256>>>(wk, wkh, HIDK, NKV * HD);
        cvt_h_transpose_kernel<<<gtk, 256>>>(wv, wvh, HIDK, NKV * HD);
        dim3 gto(HIDK / 32, HIDK / 32);
        cvt_h_transpose_kernel<<<gto, 256>>>(wo, woh, HIDK, HIDK);
    }

    const int hgemm_smem = 2 * 128 * (HPA + HPB) * (int)sizeof(__half);  // 40960
    cudaFuncSetAttribute(h_gemm_bias,
                         cudaFuncAttributeMaxDynamicSharedMemorySize, hgemm_smem);
    cudaFuncSetAttribute(h_gemm_bias_h,
                         cudaFuncAttributeMaxDynamicSharedMemorySize, hgemm_smem);

    // Projections -> fp16 (q pre-scaled by 1/sqrt(d))
    {
        dim3 gq_(HIDK / 128, MROWS / 128);
        h_gemm_bias_h<<<gq_, 256, hgemm_smem>>>(xh, wqh, bq, qh, MROWS, NH * HD, HIDK, scale);
        dim3 gk_((NKV * HD) / 128, MROWS / 128);
        h_gemm_bias_h<<<gk_, 256, hgemm_smem>>>(xh, wkh, bk, kh, MROWS, NKV * HD, HIDK, 1.0f);
        h_gemm_bias_h<<<gk_, 256, hgemm_smem>>>(xh, wvh, bv, vh, MROWS, NKV * HD, HIDK, 1.0f);
    }

    // Attention (pure fp16 dataflow), writes attnh directly
    {
        const int fl_smem = 19904 * (int)sizeof(float);   // 79616 bytes
        cudaFuncSetAttribute(flash_attn_f16_kernel,
                             cudaFuncAttributeMaxDynamicSharedMemorySize, fl_smem);
        dim3 ga(SEQ / FBR, NH, BATCH);
        flash_attn_f16_kernel<<<ga, 256, fl_smem>>>(qh, kh, vh, attnh);
    }

    // Output projection (fp32 out)
    {
        dim3 go(HIDK / 128, MROWS / 128);
        h_gemm_bias<<<go, 256, hgemm_smem>>>(attnh, woh, bo, out, MROWS, HIDK, HIDK);
    }
}

// round 17
// speedup vs baseline: 2.9644x; 1.0328x over previous
#include <cuda_runtime.h>
#include <cuda_fp16.h>
#include <math.h>
#include <stdint.h>

// Problem constants
#define HIDK   2048
#define NH     16
#define NKV    4
#define HD     128
#define BATCH  2
#define SEQ    2048
#define MROWS  (BATCH * SEQ)     // 4096

// Scratch (device globals; no allocation allowed)
__device__ __half g_qh[(size_t)MROWS * NH * HD];      // fp16 q (pre-scaled)
__device__ __half g_kh[(size_t)MROWS * NKV * HD];     // fp16 k
__device__ __half g_vh[(size_t)MROWS * NKV * HD];     // fp16 v
__device__ __half g_attnh[(size_t)MROWS * HIDK];      // fp16 attention output
__device__ __half g_xh[(size_t)MROWS * HIDK];
__device__ __half g_wqh[(size_t)(NH * HD) * HIDK];    // transposed [N][K]
__device__ __half g_wkh[(size_t)(NKV * HD) * HIDK];   // transposed
__device__ __half g_wvh[(size_t)(NKV * HD) * HIDK];   // transposed
__device__ __half g_woh[(size_t)HIDK * HIDK];         // transposed

// ---------------------------------------------------------------------------
// Common PTX helpers
// ---------------------------------------------------------------------------
__device__ __forceinline__ void mma_f16(float c[4],
                                        uint32_t a0, uint32_t a1, uint32_t a2, uint32_t a3,
                                        uint32_t b0, uint32_t b1) {
    asm volatile(
        "mma.sync.aligned.m16n8k16.row.col.f32.f16.f16.f32 "
        "{%0,%1,%2,%3}, {%4,%5,%6,%7}, {%8,%9}, {%0,%1,%2,%3};"
        : "+f"(c[0]), "+f"(c[1]), "+f"(c[2]), "+f"(c[3])
        : "r"(a0), "r"(a1), "r"(a2), "r"(a3), "r"(b0), "r"(b1));
}

#define LDSM4(r0, r1, r2, r3, addr)                                        \
    asm volatile("ldmatrix.sync.aligned.m8n8.x4.shared.b16 {%0,%1,%2,%3}, [%4];" \
                 : "=r"(r0), "=r"(r1), "=r"(r2), "=r"(r3) : "r"(addr))

__device__ __forceinline__ uint32_t smaddr(const void* p) {
    return (uint32_t)__cvta_generic_to_shared(p);
}

__device__ __forceinline__ uint32_t h2u(__half2 h) {
    return *reinterpret_cast<uint32_t*>(&h);
}
__device__ __forceinline__ __half2 u2h(uint32_t u) {
    return *reinterpret_cast<__half2*>(&u);
}

#define CPA16(dst, src) asm volatile("cp.async.cg.shared.global [%0], [%1], 16;\n" :: "r"(dst), "l"(src))
#define CPCOMMIT()      asm volatile("cp.async.commit_group;\n")
#define CPWAIT1()       asm volatile("cp.async.wait_group 1;\n" ::: "memory")
#define CPWAIT0()       asm volatile("cp.async.wait_group 0;\n" ::: "memory")

// ---------------------------------------------------------------------------
// fp32 -> fp16 elementwise convert (for x)
// ---------------------------------------------------------------------------
__global__ __launch_bounds__(256)
void cvt_h_kernel(const float* __restrict__ in, __half* __restrict__ out, int n4)
{
    int i = blockIdx.x * 256 + threadIdx.x;
    if (i < n4) {
        float4 v = ((const float4*)in)[i];
        uint2 o;
        o.x = h2u(__floats2half2_rn(v.x, v.y));
        o.y = h2u(__floats2half2_rn(v.z, v.w));
        ((uint2*)out)[i] = o;
    }
}

// ---------------------------------------------------------------------------
// fp32 [K][N] -> fp16 transposed [N][K] (for weights)
// ---------------------------------------------------------------------------
__global__ __launch_bounds__(256)
void cvt_h_transpose_kernel(const float* __restrict__ in, __half* __restrict__ out,
                            int K, int N)
{
    __shared__ float t[32][33];
    int nb = blockIdx.x * 32;
    int kb = blockIdx.y * 32;
    int tx = threadIdx.x & 31;
    int ty = threadIdx.x >> 5;     // 0..7
#pragma unroll
    for (int i = 0; i < 4; ++i)
        t[ty + i * 8][tx] = in[(size_t)(kb + ty + i * 8) * N + nb + tx];
    __syncthreads();
#pragma unroll
    for (int i = 0; i < 4; ++i)
        out[(size_t)(nb + ty + i * 8) * K + kb + tx] = __float2half_rn(t[tx][ty + i * 8]);
}

// ---------------------------------------------------------------------------
// FP16 GEMM shared body with ldmatrix fragment loads.
// A: [M][K] fp16, Bt: [N][K] fp16. 128x128 tile, BK=32, 256 thr, 2 CTAs/SM.
// Per BK step per warp: 2 ldmatrix.x4 (A) + 4 ldmatrix.x4 (B) + 32 HMMA
// (was 48 scalar LDS). Pitch 40 halves = 80B row stride -> ldmatrix phases
// conflict-free (banks 20*r (+4) mod 32 all distinct).
// ---------------------------------------------------------------------------
#define HPA 40
#define HPB 40

#define HGEMM_BODY(A, Bt, M, N, K)                                               \
    extern __shared__ __half hsm[];                                              \
    __half* As = hsm;                                                            \
    __half* Bs = hsm + 2 * 128 * HPA;                                            \
    const int tid  = threadIdx.x;                                                \
    const int lane = tid & 31;                                                   \
    const int warp = tid >> 5;                                                   \
    const int wr = warp & 3;                                                     \
    const int wc = warp >> 2;                                                    \
    const int qr = lane >> 2;                                                    \
    const int qc = lane & 3;                                                     \
    const int g  = lane >> 3;                                                    \
    const int lr = lane & 7;                                                     \
    const int rowBase = blockIdx.y * 128;                                        \
    const int colBase = blockIdx.x * 128;                                        \
    /* ldmatrix lane base addresses (bytes, buffer 0) */                         \
    const uint32_t aB0 = smaddr(As + (wr * 32 + (g & 1) * 8 + lr) * HPA + (g >> 1) * 8); \
    const uint32_t bB0 = smaddr(Bs + (wc * 64 + (g >> 1) * 8 + lr) * HPB + (g & 1) * 8); \
    const uint32_t abuf = 128 * HPA * 2;                                         \
    const uint32_t bbuf = 128 * HPB * 2;                                         \
    float acc[2][8][4];                                                          \
    _Pragma("unroll")                                                            \
    for (int m = 0; m < 2; ++m)                                                  \
        _Pragma("unroll")                                                        \
        for (int n = 0; n < 8; ++n)                                              \
            _Pragma("unroll")                                                    \
            for (int i = 0; i < 4; ++i) acc[m][n][i] = 0.f;                      \
    const int steps = K >> 5;                                                    \
    {                                                                            \
        __half* as = As;                                                         \
        __half* bs = Bs;                                                         \
        _Pragma("unroll")                                                        \
        for (int it = 0; it < 2; ++it) {                                         \
            int idx = it * 256 + tid;                                            \
            int r = idx >> 2;                                                    \
            int c = (idx & 3) << 3;                                              \
            CPA16(smaddr(as + r * HPA + c), A + (size_t)(rowBase + r) * K + c);  \
            CPA16(smaddr(bs + r * HPB + c), Bt + (size_t)(colBase + r) * K + c); \
        }                                                                        \
        CPCOMMIT();                                                              \
    }                                                                            \
    for (int s = 0; s < steps; ++s) {                                            \
        if (s + 1 < steps) {                                                     \
            int k0 = (s + 1) << 5;                                               \
            __half* as = As + ((s + 1) & 1) * 128 * HPA;                         \
            __half* bs = Bs + ((s + 1) & 1) * 128 * HPB;                         \
            _Pragma("unroll")                                                    \
            for (int it = 0; it < 2; ++it) {                                     \
                int idx = it * 256 + tid;                                        \
                int r = idx >> 2;                                                \
                int c = (idx & 3) << 3;                                          \
                CPA16(smaddr(as + r * HPA + c), A + (size_t)(rowBase + r) * K + k0 + c);  \
                CPA16(smaddr(bs + r * HPB + c), Bt + (size_t)(colBase + r) * K + k0 + c); \
            }                                                                    \
            CPCOMMIT();                                                          \
            CPWAIT1();                                                           \
        } else {                                                                 \
            CPWAIT0();                                                           \
        }                                                                        \
        __syncthreads();                                                         \
        const uint32_t aAdr = aB0 + (s & 1) * abuf;                              \
        const uint32_t bAdr = bB0 + (s & 1) * bbuf;                              \
        _Pragma("unroll")                                                        \
        for (int kk = 0; kk < 2; ++kk) {                                         \
            uint32_t af[2][4];                                                   \
            _Pragma("unroll")                                                    \
            for (int m = 0; m < 2; ++m)                                          \
                LDSM4(af[m][0], af[m][1], af[m][2], af[m][3],                    \
                      aAdr + m * (16 * HPA * 2) + kk * 32);                      \
            uint32_t bf[4][4];                                                   \
            _Pragma("unroll")                                                    \
            for (int np = 0; np < 4; ++np)                                       \
                LDSM4(bf[np][0], bf[np][1], bf[np][2], bf[np][3],                \
                      bAdr + np * (16 * HPB * 2) + kk * 32);                     \
            _Pragma("unroll")                                                    \
            for (int n = 0; n < 8; ++n) {                                        \
                uint32_t b0 = bf[n >> 1][(n & 1) * 2];                           \
                uint32_t b1 = bf[n >> 1][(n & 1) * 2 + 1];                       \
                mma_f16(acc[0][n], af[0][0], af[0][1], af[0][2], af[0][3], b0, b1); \
                mma_f16(acc[1][n], af[1][0], af[1][1], af[1][2], af[1][3], b0, b1); \
            }                                                                    \
        }                                                                        \
        __syncthreads();                                                         \
    }

// fp32-output variant (final projection)
__global__ __launch_bounds__(256, 2)
void h_gemm_bias(const __half* __restrict__ A,
                 const __half* __restrict__ Bt,
                 const float* __restrict__ bias,
                 float* __restrict__ C,
                 int M, int N, int K)
{
    HGEMM_BODY(A, Bt, M, N, K)
#pragma unroll
    for (int m = 0; m < 2; ++m) {
        int row = rowBase + wr * 32 + m * 16 + qr;
#pragma unroll
        for (int n = 0; n < 8; ++n) {
            int col = colBase + wc * 64 + n * 8 + qc * 2;
            float bx = bias[col], by = bias[col + 1];
            float2 v0 = make_float2(acc[m][n][0] + bx, acc[m][n][1] + by);
            float2 v1 = make_float2(acc[m][n][2] + bx, acc[m][n][3] + by);
            *(float2*)(C + (size_t)row * N + col)       = v0;
            *(float2*)(C + (size_t)(row + 8) * N + col) = v1;
        }
    }
}

// fp16-output variant with alpha scale (q/k/v projections)
__global__ __launch_bounds__(256, 2)
void h_gemm_bias_h(const __half* __restrict__ A,
                   const __half* __restrict__ Bt,
                   const float* __restrict__ bias,
                   __half* __restrict__ C,
                   int M, int N, int K, float alpha)
{
    HGEMM_BODY(A, Bt, M, N, K)
#pragma unroll
    for (int m = 0; m < 2; ++m) {
        int row = rowBase + wr * 32 + m * 16 + qr;
#pragma unroll
        for (int n = 0; n < 8; ++n) {
            int col = colBase + wc * 64 + n * 8 + qc * 2;
            float bx = bias[col], by = bias[col + 1];
            uint32_t w0 = h2u(__floats2half2_rn((acc[m][n][0] + bx) * alpha,
                                                (acc[m][n][1] + by) * alpha));
            uint32_t w1 = h2u(__floats2half2_rn((acc[m][n][2] + bx) * alpha,
                                                (acc[m][n][3] + by) * alpha));
            *(uint32_t*)(C + (size_t)row * N + col)       = w0;
            *(uint32_t*)(C + (size_t)(row + 8) * N + col) = w1;
        }
    }
}

// ---------------------------------------------------------------------------
// Flash attention fp16 (R16 verbatim, frozen)
// ---------------------------------------------------------------------------
#define FBR 64
#define FBC 64
#define FQP 136   // halves
#define FKP 136   // halves
#define FVP 136   // words
#define FPS 68    // floats
#define FPH 72    // halves

__global__ __launch_bounds__(256)
void flash_attn_f16_kernel(const __half* __restrict__ Q,
                           const __half* __restrict__ Kg,
                           const __half* __restrict__ Vg,
                           __half* __restrict__ Og)
{
    extern __shared__ float sm[];
    __half*    Qh = (__half*)sm;                 // [64][136] halves  (4352 f)
    __half*    Kh = (__half*)(sm + 4352);        // [64][136] halves  (4352 f)
    uint32_t*  Vh = (uint32_t*)(sm + 8704);      // [32][136] words   (4352 f)
    float*     Ps = sm + 13056;                  // [64][68] fp32     (4352 f)
    __half*    Ph = (__half*)(sm + 17408);       // [64][72] halves   (2304 f)
    float*     ms  = sm + 19712;
    float*     ls  = ms + FBR;
    float*     osc = ls + FBR;

    const int tid  = threadIdx.x;
    const int lane = tid & 31;
    const int warp = tid >> 5;
    const int wr = warp & 3;                // 4 warp rows x 16
    const int wc = warp >> 2;               // 2 warp cols
    const int qr = lane >> 2;
    const int qc = lane & 3;

    const int qt  = blockIdx.x;
    const int qh  = blockIdx.y;
    const int b   = blockIdx.z;
    const int kvh = qh >> 2;

    const int row0 = wr * 16 + qr;

    // --- Q fill: straight fp16 copy (q is pre-scaled by the projection) ---
    const __half* Qbase = Q + ((size_t)(b * SEQ + qt * FBR) * NH + qh) * HD;
#pragma unroll
    for (int it = 0; it < 4; ++it) {
        int idx = it * 256 + tid;          // 0..1023
        int r = idx >> 4;                  // row 0..63
        int c = (idx & 15) << 3;           // d octet
        *(uint4*)(Qh + r * FQP + c) =
            *(const uint4*)(Qbase + (size_t)r * NH * HD + c);
    }
    if (tid < FBR) { ms[tid] = -1e30f; ls[tid] = 0.f; }
    __syncthreads();

    // --- Q register cache (built once): qa[8][4] ---
    uint32_t qa[8][4];
#pragma unroll
    for (int kk = 0; kk < 8; ++kk) {
        const __half* qp = Qh + row0 * FQP + kk * 16 + qc * 2;
        qa[kk][0] = *(const uint32_t*)(qp);
        qa[kk][1] = *(const uint32_t*)(qp + 8 * FQP);
        qa[kk][2] = *(const uint32_t*)(qp + 8);
        qa[kk][3] = *(const uint32_t*)(qp + 8 * FQP + 8);
    }

    float o[8][4];
#pragma unroll
    for (int n = 0; n < 8; ++n)
#pragma unroll
        for (int i = 0; i < 4; ++i) o[n][i] = 0.f;

    for (int kt = 0; kt <= qt; ++kt) {
        __syncthreads();   // prior-iter reads complete before refill

        const __half* Kbase = Kg + ((size_t)(b * SEQ + kt * FBC) * NKV + kvh) * HD;
        const __half* Vbase = Vg + ((size_t)(b * SEQ + kt * FBC) * NKV + kvh) * HD;

        // K fill: straight fp16 copy.
#pragma unroll
        for (int it = 0; it < 4; ++it) {
            int idx = it * 256 + tid;
            int r = idx >> 4;
            int c = (idx & 15) << 3;
            *(uint4*)(Kh + r * FKP + c) =
                *(const uint4*)(Kbase + (size_t)r * NKV * HD + c);
        }
        // V fill: token-pair (t, t+4) interleave via half2 shuffles.
#pragma unroll
        for (int it = 0; it < 4; ++it) {
            int idx = it * 256 + tid;          // 0..1023
            int pr = idx >> 5;                 // pair row 0..31 (warp-uniform)
            int d0 = (idx & 31) << 2;          // d base (lane*4)
            int t = ((pr >> 2) << 3) + (pr & 3);
            uint2 a = *(const uint2*)(Vbase + (size_t)t * NKV * HD + d0);
            uint2 bb = *(const uint2*)(Vbase + (size_t)(t + 4) * NKV * HD + d0);
            uint4 oo;
            oo.x = h2u(__lows2half2 (u2h(a.x), u2h(bb.x)));
            oo.y = h2u(__highs2half2(u2h(a.x), u2h(bb.x)));
            oo.z = h2u(__lows2half2 (u2h(a.y), u2h(bb.y)));
            oo.w = h2u(__highs2half2(u2h(a.y), u2h(bb.y)));
            *(uint4*)(Vh + pr * FVP + d0) = oo;
        }
        __syncthreads();

        // --- S = Q @ K^T (warp: 16 rows x 32 cols), m16n8k16 ---
        float sacc[4][4];
#pragma unroll
        for (int n = 0; n < 4; ++n)
#pragma unroll
            for (int i = 0; i < 4; ++i) sacc[n][i] = 0.f;

#pragma unroll
        for (int kk = 0; kk < 8; ++kk) {
#pragma unroll
            for (int n = 0; n < 4; ++n) {
                const __half* kp = Kh + (wc * 32 + n * 8 + qr) * FKP + kk * 16 + qc * 2;
                uint32_t b0 = *(const uint32_t*)(kp);
                uint32_t b1 = *(const uint32_t*)(kp + 8);
                mma_f16(sacc[n], qa[kk][0], qa[kk][1], qa[kk][2], qa[kk][3], b0, b1);
            }
        }

        // Causal mask (diagonal tile) + store P pair-permuted to fp32 Ps.
        if (kt == qt) {
#pragma unroll
            for (int n = 0; n < 4; ++n) {
                int col = wc * 32 + n * 8 + qc * 2;
                if (col > row0)         sacc[n][0] = -1e30f;
                if (col + 1 > row0)     sacc[n][1] = -1e30f;
                if (col > row0 + 8)     sacc[n][2] = -1e30f;
                if (col + 1 > row0 + 8) sacc[n][3] = -1e30f;
            }
        }
        {
            int pc = (qc & 1) * 4 + (qc >> 1);
#pragma unroll
            for (int n = 0; n < 4; ++n) {
                int pos = (wc * 4 + n) * 8 + pc;
                Ps[row0 * FPS + pos]           = sacc[n][0];
                Ps[row0 * FPS + pos + 2]       = sacc[n][1];
                Ps[(row0 + 8) * FPS + pos]     = sacc[n][2];
                Ps[(row0 + 8) * FPS + pos + 2] = sacc[n][3];
            }
        }
        __syncthreads();

        // --- online softmax: fp32 in, writes fp16 Ph (post-exp) ---
        {
            int row = tid >> 2;
            float* pr = Ps + row * FPS + (tid & 3) * 16;
            float4 p0 = *(float4*)(pr);
            float4 p1 = *(float4*)(pr + 4);
            float4 p2 = *(float4*)(pr + 8);
            float4 p3 = *(float4*)(pr + 12);
            float rmax = fmaxf(fmaxf(fmaxf(p0.x, p0.y), fmaxf(p0.z, p0.w)),
                               fmaxf(fmaxf(p1.x, p1.y), fmaxf(p1.z, p1.w)));
            rmax = fmaxf(rmax, fmaxf(fmaxf(fmaxf(p2.x, p2.y), fmaxf(p2.z, p2.w)),
                                     fmaxf(fmaxf(p3.x, p3.y), fmaxf(p3.z, p3.w))));
            rmax = fmaxf(rmax, __shfl_xor_sync(0xffffffffu, rmax, 1));
            rmax = fmaxf(rmax, __shfl_xor_sync(0xffffffffu, rmax, 2));

            float mold = ms[row];
            float mn = fmaxf(mold, rmax);
            p0.x = __expf(p0.x - mn); p0.y = __expf(p0.y - mn);
            p0.z = __expf(p0.z - mn); p0.w = __expf(p0.w - mn);
            p1.x = __expf(p1.x - mn); p1.y = __expf(p1.y - mn);
            p1.z = __expf(p1.z - mn); p1.w = __expf(p1.w - mn);
            p2.x = __expf(p2.x - mn); p2.y = __expf(p2.y - mn);
            p2.z = __expf(p2.z - mn); p2.w = __expf(p2.w - mn);
            p3.x = __expf(p3.x - mn); p3.y = __expf(p3.y - mn);
            p3.z = __expf(p3.z - mn); p3.w = __expf(p3.w - mn);

            uint32_t* php = (uint32_t*)(Ph + row * FPH) + (tid & 3) * 8;
            php[0] = h2u(__floats2half2_rn(p0.x, p0.y));
            php[1] = h2u(__floats2half2_rn(p0.z, p0.w));
            php[2] = h2u(__floats2half2_rn(p1.x, p1.y));
            php[3] = h2u(__floats2half2_rn(p1.z, p1.w));
            php[4] = h2u(__floats2half2_rn(p2.x, p2.y));
            php[5] = h2u(__floats2half2_rn(p2.z, p2.w));
            php[6] = h2u(__floats2half2_rn(p3.x, p3.y));
            php[7] = h2u(__floats2half2_rn(p3.z, p3.w));

            float sum = (p0.x + p0.y + p0.z + p0.w) + (p1.x + p1.y + p1.z + p1.w)
                      + (p2.x + p2.y + p2.z + p2.w) + (p3.x + p3.y + p3.z + p3.w);
            sum += __shfl_xor_sync(0xffffffffu, sum, 1);
            sum += __shfl_xor_sync(0xffffffffu, sum, 2);

            if ((tid & 3) == 0) {
                float corr = __expf(mold - mn);
                ls[row] = ls[row] * corr + sum;
                ms[row] = mn;
                osc[row] = corr;
            }
        }
        __syncthreads();

        // --- rescale accumulator, O += P @ V (m16n8k16, permuted k) ---
        {
            float c0 = osc[row0];
            float c1 = osc[row0 + 8];
#pragma unroll
            for (int n = 0; n < 8; ++n) {
                o[n][0] *= c0; o[n][1] *= c0;
                o[n][2] *= c1; o[n][3] *= c1;
            }
        }
#pragma unroll
        for (int kk = 0; kk < 4; ++kk) {
            const __half* pp = Ph + row0 * FPH + kk * 16 + qc * 2;
            uint32_t a0 = *(const uint32_t*)(pp);
            uint32_t a1 = *(const uint32_t*)(pp + 8 * FPH);
            uint32_t a2 = *(const uint32_t*)(pp + 8);
            uint32_t a3 = *(const uint32_t*)(pp + 8 * FPH + 8);
#pragma unroll
            for (int n = 0; n < 8; ++n) {
                int d = wc * 64 + n * 8 + qr;
                uint32_t b0 = Vh[(8 * kk + qc) * FVP + d];
                uint32_t b1 = Vh[(8 * kk + 4 + qc) * FVP + d];
                mma_f16(o[n], a0, a1, a2, a3, b0, b1);
            }
        }
    }

    // Final 1/l normalization + fp16 store.
    float inv0 = 1.f / ls[row0];
    float inv1 = 1.f / ls[row0 + 8];
    int srow0 = b * SEQ + qt * FBR + row0;
#pragma unroll
    for (int n = 0; n < 8; ++n) {
        int col = wc * 64 + n * 8 + qc * 2;
        __half* p0 = Og + ((size_t)srow0 * NH + qh) * HD + col;
        __half* p1 = Og + ((size_t)(srow0 + 8) * NH + qh) * HD + col;
        *(uint32_t*)p0 = h2u(__floats2half2_rn(o[n][0] * inv0, o[n][1] * inv0));
        *(uint32_t*)p1 = h2u(__floats2half2_rn(o[n][2] * inv1, o[n][3] * inv1));
    }
}

// ---------------------------------------------------------------------------
// Launcher
// ---------------------------------------------------------------------------
extern "C" void kernel_launch(void* const* d_in, const int* in_sizes, int n_in,
                              void* d_out, int out_size)
{
    const float* x  = (const float*)d_in[0];
    const float* wq = (const float*)d_in[1];
    const float* bq = (const float*)d_in[2];
    const float* wk = (const float*)d_in[3];
    const float* bk = (const float*)d_in[4];
    const float* wv = (const float*)d_in[5];
    const float* bv = (const float*)d_in[6];
    const float* wo = (const float*)d_in[7];
    const float* bo = (const float*)d_in[8];
    float* out = (float*)d_out;

    __half *qh, *kh, *vh, *attnh, *xh, *wqh, *wkh, *wvh, *woh;
    cudaGetSymbolAddress((void**)&qh,    g_qh);
    cudaGetSymbolAddress((void**)&kh,    g_kh);
    cudaGetSymbolAddress((void**)&vh,    g_vh);
    cudaGetSymbolAddress((void**)&attnh, g_attnh);
    cudaGetSymbolAddress((void**)&xh,    g_xh);
    cudaGetSymbolAddress((void**)&wqh,   g_wqh);
    cudaGetSymbolAddress((void**)&wkh,   g_wkh);
    cudaGetSymbolAddress((void**)&wvh,   g_wvh);
    cudaGetSymbolAddress((void**)&woh,   g_woh);

    const float scale = 0.08838834764831845f;  // 1/sqrt(128)

    // fp16 pre-conversion: x elementwise; weights converted + transposed
    {
        int n4x = (MROWS * HIDK) / 4;
        cvt_h_kernel<<<(n4x + 255) / 256, 256>>>(x, xh, n4x);
        dim3 gtq((NH * HD) / 32, HIDK / 32);
        cvt_h_transpose_kernel<<<gtq, 256>>>(wq, wqh, HIDK, NH * HD);
        dim3 gtk((NKV * HD) / 32, HIDK / 32);
        cvt_h_transpose_kernel<<<gtk, 256>>>(wk, wkh, HIDK, NKV * HD);
        cvt_h_transpose_kernel<<<gtk, 256>>>(wv, wvh, HIDK, NKV * HD);
        dim3 gto(HIDK / 32, HIDK / 32);
        cvt_h_transpose_kernel<<<gto, 256>>>(wo, woh, HIDK, HIDK);
    }

    const int hgemm_smem = 2 * 128 * (HPA + HPB) * (int)sizeof(__half);  // 40960
    cudaFuncSetAttribute(h_gemm_bias,
                         cudaFuncAttributeMaxDynamicSharedMemorySize, hgemm_smem);
    cudaFuncSetAttribute(h_gemm_bias_h,
                         cudaFuncAttributeMaxDynamicSharedMemorySize, hgemm_smem);

    // Projections -> fp16 (q pre-scaled by 1/sqrt(d))
    {
        dim3 gq_(HIDK / 128, MROWS / 128);
        h_gemm_bias_h<<<gq_, 256, hgemm_smem>>>(xh, wqh, bq, qh, MROWS, NH * HD, HIDK, scale);
        dim3 gk_((NKV * HD) / 128, MROWS / 128);
        h_gemm_bias_h<<<gk_, 256, hgemm_smem>>>(xh, wkh, bk, kh, MROWS, NKV * HD, HIDK, 1.0f);
        h_gemm_bias_h<<<gk_, 256, hgemm_smem>>>(xh, wvh, bv, vh, MROWS, NKV * HD, HIDK, 1.0f);
    }

    // Attention (pure fp16 dataflow), writes attnh directly
    {
        const int fl_smem = 19904 * (int)sizeof(float);   // 79616 bytes
        cudaFuncSetAttribute(flash_attn_f16_kernel,
                             cudaFuncAttributeMaxDynamicSharedMemorySize, fl_smem);
        dim3 ga(SEQ / FBR, NH, BATCH);
        flash_attn_f16_kernel<<<ga, 256, fl_smem>>>(qh, kh, vh, attnh);
    }

    // Output projection (fp32 out)
    {
        dim3 go(HIDK / 128, MROWS / 128);
        h_gemm_bias<<<go, 256, hgemm_smem>>>(attnh, woh, bo, out, MROWS, HIDK, HIDK);
    }
}